// round 7
// baseline (speedup 1.0000x reference)
#include <cuda_runtime.h>
#include <cuda_fp16.h>
#include <math.h>
#include <stdint.h>

#define NM 100000
#define ND 20000
#define NA 50000
#define E0 300000
#define ETOT 600000
#define NB 98            // ceil(NM/1024)
#define GEMM_BLKS 1878   // 782 q0 + 1096 kv
#define CNT_BLKS 586     // 586*1024 >= ETOT

// ---------------- scratch (static device memory; no allocs) ----------------
__device__ __half d_q0h[NM * 128];
__device__ float  d_s0[NM * 8];
__device__ __half d_ktdm[ND * 128];
__device__ __half d_mtdm[ND * 128];
__device__ __half d_ktam[NA * 128];
__device__ __half d_mtam[NA * 128];
__device__ int    d_counts[NM];
__device__ int    d_cursor[NM];
__device__ int    d_rowptr[NM + 1];
__device__ int    d_scanState[NB];   // packed: (flag<<24) | aggregate ; memset 0 per run
__device__ int    d_epay[ETOT];      // packed: src | (rel<<31)

__device__ float d_WeffK0[128 * 128], d_WeffV0[128 * 128];
__device__ float d_WeffK1[128 * 128], d_WeffV1[128 * 128];
__device__ float d_beffK0[128], d_beffV0[128], d_beffK1[128], d_beffV1[128];
__device__ float d_WK0[128 * 128], d_WV0[128 * 128], d_WK1[128 * 128], d_WV1[128 * 128];
__device__ float d_bK0[128], d_bV0[128], d_bK1[128], d_bV1[128];
__device__ float d_Wqf[256 * 128];
__device__ float d_bqf[128];
__device__ float d_Wsf[256 * 8];
__device__ float d_bsf[8];
__device__ float d_Wcomb[128 * 8];
__device__ float d_tmp8[8];

// ---------------- fused weight-composition kernels ----------------

__global__ void prep_compose(const float* __restrict__ Wk, const float* __restrict__ bk,
                             const float* __restrict__ Wv, const float* __restrict__ bv,
                             const float* __restrict__ a_rel, const float* __restrict__ m_rel) {
    int which = blockIdx.x / 129;
    int i = blockIdx.x - which * 129;
    const float *Win, *bin, *A; float *Weff, *beff;
    switch (which) {
        case 0: Win = Wk + 16384; bin = bk + 128; A = a_rel;        Weff = d_WeffK0; beff = d_beffK0; break;
        case 1: Win = Wk + 32768; bin = bk + 256; A = a_rel + 2048; Weff = d_WeffK1; beff = d_beffK1; break;
        case 2: Win = Wv + 16384; bin = bv + 128; A = m_rel;        Weff = d_WeffV0; beff = d_beffV0; break;
        default:Win = Wv + 32768; bin = bv + 256; A = m_rel + 2048; Weff = d_WeffV1; beff = d_beffV1; break;
    }
    int col = threadIdx.x;
    int h = col >> 4, f = col & 15;
    const float* arow = A + h * 256 + f;
    const float* w = (i < 128) ? (Win + i * 128 + h * 16) : (bin + h * 16);
    float s = 0.f;
#pragma unroll
    for (int d = 0; d < 16; d++) s += w[d] * arow[d * 16];
    if (i < 128) Weff[i * 128 + col] = s;
    else         beff[col] = s;
}

__device__ __forceinline__ void mm_task(const float* __restrict__ A, const float* __restrict__ B,
                                        const float* __restrict__ add, float* __restrict__ C,
                                        int M, int K, int N, int t) {
    if (t >= M * N) return;
    int m = t / N, n = t - m * N;
    float s = add ? add[n] : 0.f;
    for (int k = 0; k < K; k++) s += A[m * K + k] * B[k * N + n];
    C[t] = s;
}

__global__ void prep_mm(const float* __restrict__ Wpre_m, const float* __restrict__ Wpre_d,
                        const float* __restrict__ Wpre_a, const float* __restrict__ bpre,
                        const float* __restrict__ Wq, const float* __restrict__ bq,
                        const float* __restrict__ Wa, const float* __restrict__ ba,
                        const float* __restrict__ Wlin) {
    int b = blockIdx.x;
    int tid = threadIdx.x;
    if (b < 64)        mm_task(Wpre_d, d_WeffK0, nullptr, d_WK0, 128, 128, 128, b * 256 + tid);
    else if (b < 128)  mm_task(Wpre_d, d_WeffV0, nullptr, d_WV0, 128, 128, 128, (b - 64) * 256 + tid);
    else if (b < 192)  mm_task(Wpre_a, d_WeffK1, nullptr, d_WK1, 128, 128, 128, (b - 128) * 256 + tid);
    else if (b < 256)  mm_task(Wpre_a, d_WeffV1, nullptr, d_WV1, 128, 128, 128, (b - 192) * 256 + tid);
    else if (b < 384)  mm_task(Wpre_m, Wq, nullptr, d_Wqf, 256, 128, 128, (b - 256) * 256 + tid);
    else if (b == 384) mm_task(bpre + 128, d_WeffK0, d_beffK0, d_bK0, 1, 128, 128, tid);
    else if (b == 385) mm_task(bpre + 128, d_WeffV0, d_beffV0, d_bV0, 1, 128, 128, tid);
    else if (b == 386) mm_task(bpre + 256, d_WeffK1, d_beffK1, d_bK1, 1, 128, 128, tid);
    else if (b == 387) mm_task(bpre + 256, d_WeffV1, d_beffV1, d_bV1, 1, 128, 128, tid);
    else if (b == 388) mm_task(bpre, Wq, bq, d_bqf, 1, 128, 128, tid);
    else if (b < 397)  mm_task(Wpre_m, Wlin, nullptr, d_Wsf, 256, 128, 8, (b - 389) * 256 + tid);
    else if (b == 397) mm_task(bpre, Wlin, nullptr, d_bsf, 1, 128, 8, tid);
    else if (b < 402)  mm_task(Wa, Wlin, nullptr, d_Wcomb, 128, 128, 8, (b - 398) * 256 + tid);
    else               mm_task(ba, Wlin, nullptr, d_tmp8, 1, 128, 8, tid);
}

// ---------------- pipelined tf32 tensor-core GEMM ----------------
__device__ __forceinline__ void cpa16(void* s, const void* g, int psz) {
    uint32_t sa = (uint32_t)__cvta_generic_to_shared(s);
    asm volatile("cp.async.cg.shared.global [%0], [%1], 16, %2;" :: "r"(sa), "l"(g), "r"(psz));
}

template<int KT, bool FS0, bool HOUT>
__device__ __forceinline__ void gemm_body(const float* __restrict__ A, const float* __restrict__ W,
                                          const float* __restrict__ bias, void* __restrict__ Cv,
                                          int M, int row0,
                                          const float* __restrict__ Wsf, const float* __restrict__ bsf,
                                          float* __restrict__ S) {
    extern __shared__ float smem[];
    float* AsBase = smem;                 // 2 * 128 * 36 = 9216
    float* BsBase = smem + 9216;          // 2 * 32 * 136 = 8704
    float* sWs    = smem + 9216 + 8704;   // 2048

    const int K = KT * 32;
    int tid = threadIdx.x;
    int warp = tid >> 5, lane = tid & 31;
    int wm = warp >> 1, wn = warp & 1;
    int g = lane >> 2, tg = lane & 3;

    if (FS0) {
        for (int i = tid; i < 2048; i += 256) sWs[i] = Wsf[i];
    }

    float acc[2][8][4];
#pragma unroll
    for (int mi = 0; mi < 2; mi++)
#pragma unroll
        for (int ni = 0; ni < 8; ni++)
#pragma unroll
            for (int c = 0; c < 4; c++) acc[mi][ni][c] = 0.f;
    float sacc[4] = {0.f, 0.f, 0.f, 0.f};

    auto load_tile = [&](int kt, int buf) {
        float* Ab = AsBase + buf * (128 * 36);
        float* Bb = BsBase + buf * (32 * 136);
#pragma unroll
        for (int l = 0; l < 4; l++) {
            int cidx = tid + l * 256;
            int r = cidx >> 3, q = cidx & 7;
            int gr = row0 + r;
            const float* ga = (gr < M) ? &A[(size_t)gr * K + kt * 32 + q * 4] : A;
            cpa16(&Ab[r * 36 + q * 4], ga, (gr < M) ? 16 : 0);
        }
#pragma unroll
        for (int l = 0; l < 4; l++) {
            int cidx = tid + l * 256;
            int k = cidx >> 5, q = cidx & 31;
            cpa16(&Bb[k * 136 + q * 4], &W[(size_t)(kt * 32 + k) * 128 + q * 4], 16);
        }
        asm volatile("cp.async.commit_group;");
    };

    load_tile(0, 0);

    for (int t = 0; t < KT; t++) {
        if (t + 1 < KT) {
            load_tile(t + 1, (t + 1) & 1);
            asm volatile("cp.async.wait_group 1;");
        } else {
            asm volatile("cp.async.wait_group 0;");
        }
        __syncthreads();

        float* Ab = AsBase + (t & 1) * (128 * 36);
        float* Bb = BsBase + (t & 1) * (32 * 136);

#pragma unroll
        for (int ks = 0; ks < 32; ks += 8) {
            uint32_t a_[2][4];
#pragma unroll
            for (int mi = 0; mi < 2; mi++) {
                int ar = wm * 32 + mi * 16 + g;
                a_[mi][0] = __float_as_uint(Ab[ar * 36 + ks + tg]);
                a_[mi][1] = __float_as_uint(Ab[(ar + 8) * 36 + ks + tg]);
                a_[mi][2] = __float_as_uint(Ab[ar * 36 + ks + tg + 4]);
                a_[mi][3] = __float_as_uint(Ab[(ar + 8) * 36 + ks + tg + 4]);
            }
#pragma unroll
            for (int ni = 0; ni < 8; ni++) {
                int bc = wn * 64 + ni * 8 + g;
                uint32_t b0 = __float_as_uint(Bb[(ks + tg) * 136 + bc]);
                uint32_t b1 = __float_as_uint(Bb[(ks + tg + 4) * 136 + bc]);
#pragma unroll
                for (int mi = 0; mi < 2; mi++) {
                    asm volatile(
                        "mma.sync.aligned.m16n8k8.row.col.f32.tf32.tf32.f32 "
                        "{%0,%1,%2,%3}, {%4,%5,%6,%7}, {%8,%9}, {%0,%1,%2,%3};"
                        : "+f"(acc[mi][ni][0]), "+f"(acc[mi][ni][1]),
                          "+f"(acc[mi][ni][2]), "+f"(acc[mi][ni][3])
                        : "r"(a_[mi][0]), "r"(a_[mi][1]), "r"(a_[mi][2]), "r"(a_[mi][3]),
                          "r"(b0), "r"(b1));
                }
            }
        }

        if (FS0) {
            int r = tid >> 1, cg4 = (tid & 1) * 4;
            const float* Ar = &Ab[r * 36];
            const float* Wr = &sWs[t * 32 * 8 + cg4];
#pragma unroll
            for (int kk = 0; kk < 32; kk++) {
                float av = Ar[kk];
                float4 w = *(const float4*)&Wr[kk * 8];
                sacc[0] += av * w.x; sacc[1] += av * w.y;
                sacc[2] += av * w.z; sacc[3] += av * w.w;
            }
        }
        __syncthreads();
    }

#pragma unroll
    for (int mi = 0; mi < 2; mi++) {
#pragma unroll
        for (int ni = 0; ni < 8; ni++) {
            int col = wn * 64 + ni * 8 + tg * 2;
            float bx = bias[col], by = bias[col + 1];
            int r1 = row0 + wm * 32 + mi * 16 + g;
            int r2 = r1 + 8;
            if (HOUT) {
                __half* C = (__half*)Cv;
                if (r1 < M)
                    *(__half2*)&C[(size_t)r1 * 128 + col] =
                        __floats2half2_rn(acc[mi][ni][0] + bx, acc[mi][ni][1] + by);
                if (r2 < M)
                    *(__half2*)&C[(size_t)r2 * 128 + col] =
                        __floats2half2_rn(acc[mi][ni][2] + bx, acc[mi][ni][3] + by);
            } else {
                float* C = (float*)Cv;
                if (r1 < M) {
                    float2 o = make_float2(acc[mi][ni][0] + bx, acc[mi][ni][1] + by);
                    *(float2*)&C[(size_t)r1 * 128 + col] = o;
                }
                if (r2 < M) {
                    float2 o = make_float2(acc[mi][ni][2] + bx, acc[mi][ni][3] + by);
                    *(float2*)&C[(size_t)r2 * 128 + col] = o;
                }
            }
        }
    }

    if (FS0) {
        int r = tid >> 1, cg4 = (tid & 1) * 4;
        int gr = row0 + r;
        if (gr < M) {
            float4 o;
            o.x = sacc[0] + bsf[cg4 + 0];
            o.y = sacc[1] + bsf[cg4 + 1];
            o.z = sacc[2] + bsf[cg4 + 2];
            o.w = sacc[3] + bsf[cg4 + 3];
            *(float4*)&S[(size_t)gr * 8 + cg4] = o;
        }
    }
}

// merged launch: q0 (fp16 out + fused s0) + 4 K/V GEMMs + edge counting (extra blocks)
__global__ __launch_bounds__(256, 2)
void gemm_all(const float* __restrict__ x_m, const float* __restrict__ x_d,
              const float* __restrict__ x_a,
              const int* __restrict__ dst_dm, const int* __restrict__ dst_am) {
    int b = blockIdx.x;
    if (b >= GEMM_BLKS) {   // edge-count blocks (overlap with GEMM)
        int b2 = b - GEMM_BLKS;
#pragma unroll
        for (int j = 0; j < 4; j++) {
            int e = b2 * 1024 + j * 256 + threadIdx.x;
            if (e < E0) atomicAdd(&d_counts[dst_dm[e]], 1);
            else if (e < ETOT) atomicAdd(&d_counts[dst_am[e - E0]], 1);
        }
        return;
    }
    if (b < 782) {
        gemm_body<8, true, true>(x_m, d_Wqf, d_bqf, d_q0h, NM, b * 128, d_Wsf, d_bsf, d_s0);
        return;
    }
    b -= 782;
    if (b < 157)      gemm_body<4, false, true>(x_d, d_WK0, d_bK0, d_ktdm, ND, b * 128, nullptr, nullptr, nullptr);
    else if (b < 314) gemm_body<4, false, true>(x_d, d_WV0, d_bV0, d_mtdm, ND, (b - 157) * 128, nullptr, nullptr, nullptr);
    else if (b < 705) gemm_body<4, false, true>(x_a, d_WK1, d_bK1, d_ktam, NA, (b - 314) * 128, nullptr, nullptr, nullptr);
    else              gemm_body<4, false, true>(x_a, d_WV1, d_bV1, d_mtam, NA, (b - 705) * 128, nullptr, nullptr, nullptr);
}

// ---------------- single-kernel scan (decoupled lookback) ----------------
// State is self-contained (flag + aggregate packed in one int), so relaxed atomics suffice.
__global__ __launch_bounds__(1024)
void scan_fused() {
    __shared__ int sh[1024];
    __shared__ int s_prefix;
    int b = blockIdx.x;
    int i = b * 1024 + threadIdx.x;
    int v = (i < NM) ? d_counts[i] : 0;
    sh[threadIdx.x] = v;
    __syncthreads();
    for (int off = 1; off < 1024; off <<= 1) {
        int t = (threadIdx.x >= off) ? sh[threadIdx.x - off] : 0;
        __syncthreads();
        sh[threadIdx.x] += t;
        __syncthreads();
    }
    int total = sh[1023];

    if (threadIdx.x == 0) {
        if (b == 0) {
            atomicExch(&d_scanState[0], (2 << 24) | total);  // inclusive ready
            s_prefix = 0;
        } else {
            atomicExch(&d_scanState[b], (1 << 24) | total);  // aggregate ready
            int running = 0;
            int p = b - 1;
            while (true) {
                int s = atomicAdd(&d_scanState[p], 0);
                int flag = s >> 24;
                if (flag == 0) continue;            // not published yet, spin
                running += s & 0xFFFFFF;
                if (flag == 2) break;               // found inclusive prefix
                p--;
            }
            atomicExch(&d_scanState[b], (2 << 24) | (running + total));
            s_prefix = running;
        }
    }
    __syncthreads();
    int prefix = s_prefix;
    if (i < NM) {
        int excl = prefix + sh[threadIdx.x] - v;
        d_rowptr[i] = excl;
        d_cursor[i] = excl;
    }
    if (b == NB - 1 && threadIdx.x == 1023) d_rowptr[NM] = ETOT;
}

// scatter packed payload: src index | rel bit
__global__ void fill_edges(const int* __restrict__ dst_dm, const int* __restrict__ dst_am,
                           const int* __restrict__ src_dm, const int* __restrict__ src_am) {
#pragma unroll
    for (int j = 0; j < 4; j++) {
        int e = blockIdx.x * 1024 + j * 256 + threadIdx.x;
        int d, pay;
        if (e < E0)        { d = dst_dm[e];      pay = src_dm[e]; }
        else if (e < ETOT) { d = dst_am[e - E0]; pay = src_am[e - E0] | 0x80000000; }
        else continue;
        int pos = atomicAdd(&d_cursor[d], 1);
        d_epay[pos] = pay;
    }
}

// ---------------- fused: per-edge attention + softmax-agg + gelu + output head ----------------
__device__ __forceinline__ float gelu_exact(float x) { return x * normcdff(x); }

__device__ __forceinline__ float4 half8_to_f4(const __half* base, size_t off) {
    uint2 w = *(const uint2*)(base + off);
    float2 lo = __half22float2(*(__half2*)&w.x);
    float2 hi = __half22float2(*(__half2*)&w.y);
    return make_float4(lo.x, lo.y, hi.x, hi.y);
}

__global__ __launch_bounds__(256)
void agg_out(const float* __restrict__ p_rel, const float* __restrict__ skip,
             const float* __restrict__ blin, float* __restrict__ out) {
    __shared__ float sWc[128 * 8];
    __shared__ float sc[9];
    for (int i = threadIdx.x; i < 1024; i += 256) sWc[i] = d_Wcomb[i];
    if (threadIdx.x < 8) {
        float gg = 1.f / (1.f + expf(-skip[0]));
        sc[1 + threadIdx.x] = gg * d_tmp8[threadIdx.x] + blin[threadIdx.x];
        if (threadIdx.x == 0) sc[0] = gg;
    }
    __syncthreads();

    int warp = threadIdx.x >> 5, lane = threadIdx.x & 31;
    int node = blockIdx.x * 8 + warp;
    int h = lane >> 2;
    const float scale = 0.25f;
    float p0 = p_rel[h] * scale;
    float p1 = p_rel[8 + h] * scale;

    float4 qv = half8_to_f4(d_q0h, (size_t)node * 128 + lane * 4);
    int beg = d_rowptr[node], end = d_rowptr[node + 1];

    float4 acc = make_float4(0.f, 0.f, 0.f, 0.f);
    float den = 0.f;
    int i = beg;
    // unroll-4: issue all 4 payloads + 8 vector gathers before consuming (high MLP)
    for (; i + 4 <= end; i += 4) {
        int   pay[4];
        float ph[4];
        float4 kf[4], mf[4];
#pragma unroll
        for (int j = 0; j < 4; j++) pay[j] = d_epay[i + j];
#pragma unroll
        for (int j = 0; j < 4; j++) {
            unsigned u = (unsigned)pay[j];
            int src = pay[j] & 0x7FFFFFFF;
            const __half* kb = (u >> 31) ? d_ktam : d_ktdm;
            const __half* mb = (u >> 31) ? d_mtam : d_mtdm;
            ph[j] = (u >> 31) ? p1 : p0;
            size_t base = (size_t)src * 128 + lane * 4;
            kf[j] = half8_to_f4(kb, base);
            mf[j] = half8_to_f4(mb, base);
        }
        float dd[4];
#pragma unroll
        for (int j = 0; j < 4; j++)
            dd[j] = qv.x * kf[j].x + qv.y * kf[j].y + qv.z * kf[j].z + qv.w * kf[j].w;
#pragma unroll
        for (int j = 0; j < 4; j++) dd[j] += __shfl_xor_sync(0xffffffffu, dd[j], 1);
#pragma unroll
        for (int j = 0; j < 4; j++) dd[j] += __shfl_xor_sync(0xffffffffu, dd[j], 2);
#pragma unroll
        for (int j = 0; j < 4; j++) {
            float a = __expf(dd[j] * ph[j]);
            den += a;
            acc.x += a * mf[j].x; acc.y += a * mf[j].y;
            acc.z += a * mf[j].z; acc.w += a * mf[j].w;
        }
    }
    for (; i < end; i++) {
        int pay = d_epay[i];
        unsigned u = (unsigned)pay;
        int src = pay & 0x7FFFFFFF;
        const __half* kb = (u >> 31) ? d_ktam : d_ktdm;
        const __half* mb = (u >> 31) ? d_mtam : d_mtdm;
        float ph = (u >> 31) ? p1 : p0;
        size_t base = (size_t)src * 128 + lane * 4;
        float4 k0 = half8_to_f4(kb, base);
        float4 m0 = half8_to_f4(mb, base);
        float d0 = qv.x * k0.x + qv.y * k0.y + qv.z * k0.z + qv.w * k0.w;
        d0 += __shfl_xor_sync(0xffffffffu, d0, 1);
        d0 += __shfl_xor_sync(0xffffffffu, d0, 2);
        float a0 = __expf(d0 * ph);
        den += a0;
        acc.x += a0 * m0.x; acc.y += a0 * m0.y;
        acc.z += a0 * m0.z; acc.w += a0 * m0.w;
    }

    float inv = (den > 0.f) ? (1.f / den) : 0.f;
    float gl[4];
    gl[0] = gelu_exact(acc.x * inv);
    gl[1] = gelu_exact(acc.y * inv);
    gl[2] = gelu_exact(acc.z * inv);
    gl[3] = gelu_exact(acc.w * inv);

    float o[8] = {0, 0, 0, 0, 0, 0, 0, 0};
    int r0 = lane * 4;
#pragma unroll
    for (int j = 0; j < 4; j++) {
        float gj = gl[j];
        const float* wr = &sWc[(r0 + j) * 8];
#pragma unroll
        for (int c = 0; c < 8; c++) o[c] += gj * wr[c];
    }
#pragma unroll
    for (int off = 16; off > 0; off >>= 1)
#pragma unroll
        for (int c = 0; c < 8; c++) o[c] += __shfl_xor_sync(0xffffffffu, o[c], off);

    if (lane == 0) {
        float g = sc[0];
        const float* s0p = &d_s0[(size_t)node * 8];
        float4 o1, o2;
        o1.x = g * o[0] + (1.f - g) * s0p[0] + sc[1];
        o1.y = g * o[1] + (1.f - g) * s0p[1] + sc[2];
        o1.z = g * o[2] + (1.f - g) * s0p[2] + sc[3];
        o1.w = g * o[3] + (1.f - g) * s0p[3] + sc[4];
        o2.x = g * o[4] + (1.f - g) * s0p[4] + sc[5];
        o2.y = g * o[5] + (1.f - g) * s0p[5] + sc[6];
        o2.z = g * o[6] + (1.f - g) * s0p[6] + sc[7];
        o2.w = g * o[7] + (1.f - g) * s0p[7] + sc[8];
        *(float4*)&out[(size_t)node * 8] = o1;
        *(float4*)&out[(size_t)node * 8 + 4] = o2;
    }
}

// ---------------- launch ----------------
#define SYM(p, s) cudaGetSymbolAddress((void**)&(p), s)

extern "C" void kernel_launch(void* const* d_in, const int* in_sizes, int n_in,
                              void* d_out, int out_size) {
    (void)in_sizes; (void)n_in; (void)out_size;
    const float* x_m   = (const float*)d_in[0];
    const float* x_d   = (const float*)d_in[1];
    const float* x_a   = (const float*)d_in[2];
    const int* src_dm  = (const int*)d_in[3];
    const int* dst_dm  = (const int*)d_in[4];
    const int* src_am  = (const int*)d_in[5];
    const int* dst_am  = (const int*)d_in[6];
    const float* Wpre_m = (const float*)d_in[11];
    const float* Wpre_d = (const float*)d_in[12];
    const float* Wpre_a = (const float*)d_in[13];
    const float* bpre   = (const float*)d_in[14];
    const float* Wk     = (const float*)d_in[15];
    const float* bk     = (const float*)d_in[16];
    const float* Wq     = (const float*)d_in[17];
    const float* bq     = (const float*)d_in[18];
    const float* Wv     = (const float*)d_in[19];
    const float* bv     = (const float*)d_in[20];
    const float* a_rel  = (const float*)d_in[21];
    const float* m_rel  = (const float*)d_in[22];
    const float* p_rel  = (const float*)d_in[23];
    const float* skip   = (const float*)d_in[24];
    const float* Wa     = (const float*)d_in[25];
    const float* ba     = (const float*)d_in[26];
    const float* Wlin   = (const float*)d_in[27];
    const float* blin   = (const float*)d_in[28];
    float* out = (float*)d_out;

    int *counts, *scanState;
    SYM(counts, d_counts);
    SYM(scanState, d_scanState);

    const int SMEM_G = (9216 + 8704 + 2048) * 4;   // 79872 B
    static int attr_set = 0;
    if (!attr_set) {
        cudaFuncSetAttribute(gemm_all, cudaFuncAttributeMaxDynamicSharedMemorySize, SMEM_G);
        attr_set = 1;
    }

    // 1) clears + weight prep
    cudaMemsetAsync(counts, 0, NM * sizeof(int));
    cudaMemsetAsync(scanState, 0, NB * sizeof(int));
    prep_compose<<<516, 128>>>(Wk, bk, Wv, bv, a_rel, m_rel);
    prep_mm<<<403, 256>>>(Wpre_m, Wpre_d, Wpre_a, bpre, Wq, bq, Wa, ba, Wlin);

    // 2) all node-level GEMMs + edge counting in one launch (counting overlaps GEMM)
    gemm_all<<<GEMM_BLKS + CNT_BLKS, 256, SMEM_G>>>(x_m, x_d, x_a, dst_dm, dst_am);

    // 3) CSR: single-kernel decoupled-lookback scan, then scatter
    scan_fused<<<NB, 1024>>>();
    fill_edges<<<586, 256>>>(dst_dm, dst_am, src_dm, src_am);

    // 4) fused attention + softmax aggregation + gelu + output head
    agg_out<<<12500, 256>>>(p_rel, skip, blin, out);
}

// round 8
// speedup vs baseline: 1.0484x; 1.0484x over previous
#include <cuda_runtime.h>
#include <cuda_fp16.h>
#include <math.h>
#include <stdint.h>

#define NM 100000
#define ND 20000
#define NA 50000
#define E0 300000
#define ETOT 600000
#define NB 98   // ceil(NM/1024)

// ---------------- scratch (static device memory; no allocs) ----------------
__device__ __half d_q0h[NM * 128];
__device__ float  d_s0[NM * 8];
__device__ __half d_ktdm[ND * 128];
__device__ __half d_mtdm[ND * 128];
__device__ __half d_ktam[NA * 128];
__device__ __half d_mtam[NA * 128];
__device__ int    d_counts[NM];
__device__ int    d_cursor[NM];
__device__ int    d_rowptr[NM + 1];
__device__ int    d_bsum[128];
__device__ int    d_epay[ETOT];   // packed: src | (rel<<31)

__device__ float d_WeffK0[128 * 128], d_WeffV0[128 * 128];
__device__ float d_WeffK1[128 * 128], d_WeffV1[128 * 128];
__device__ float d_beffK0[128], d_beffV0[128], d_beffK1[128], d_beffV1[128];
__device__ float d_WK0[128 * 128], d_WV0[128 * 128], d_WK1[128 * 128], d_WV1[128 * 128];
__device__ float d_bK0[128], d_bV0[128], d_bK1[128], d_bV1[128];
__device__ float d_Wqf[256 * 128];
__device__ float d_bqf[128];
__device__ float d_Wsf[256 * 8];
__device__ float d_bsf[8];
__device__ float d_Wcomb[128 * 8];
__device__ float d_tmp8[8];

// ---------------- fused weight-composition kernels ----------------

__global__ void prep_compose(const float* __restrict__ Wk, const float* __restrict__ bk,
                             const float* __restrict__ Wv, const float* __restrict__ bv,
                             const float* __restrict__ a_rel, const float* __restrict__ m_rel) {
    int which = blockIdx.x / 129;
    int i = blockIdx.x - which * 129;
    const float *Win, *bin, *A; float *Weff, *beff;
    switch (which) {
        case 0: Win = Wk + 16384; bin = bk + 128; A = a_rel;        Weff = d_WeffK0; beff = d_beffK0; break;
        case 1: Win = Wk + 32768; bin = bk + 256; A = a_rel + 2048; Weff = d_WeffK1; beff = d_beffK1; break;
        case 2: Win = Wv + 16384; bin = bv + 128; A = m_rel;        Weff = d_WeffV0; beff = d_beffV0; break;
        default:Win = Wv + 32768; bin = bv + 256; A = m_rel + 2048; Weff = d_WeffV1; beff = d_beffV1; break;
    }
    int col = threadIdx.x;
    int h = col >> 4, f = col & 15;
    const float* arow = A + h * 256 + f;
    const float* w = (i < 128) ? (Win + i * 128 + h * 16) : (bin + h * 16);
    float s = 0.f;
#pragma unroll
    for (int d = 0; d < 16; d++) s += w[d] * arow[d * 16];
    if (i < 128) Weff[i * 128 + col] = s;
    else         beff[col] = s;
}

__device__ __forceinline__ void mm_task(const float* __restrict__ A, const float* __restrict__ B,
                                        const float* __restrict__ add, float* __restrict__ C,
                                        int M, int K, int N, int t) {
    if (t >= M * N) return;
    int m = t / N, n = t - m * N;
    float s = add ? add[n] : 0.f;
    for (int k = 0; k < K; k++) s += A[m * K + k] * B[k * N + n];
    C[t] = s;
}

__global__ void prep_mm(const float* __restrict__ Wpre_m, const float* __restrict__ Wpre_d,
                        const float* __restrict__ Wpre_a, const float* __restrict__ bpre,
                        const float* __restrict__ Wq, const float* __restrict__ bq,
                        const float* __restrict__ Wa, const float* __restrict__ ba,
                        const float* __restrict__ Wlin) {
    int b = blockIdx.x;
    int tid = threadIdx.x;
    if (b < 64)        mm_task(Wpre_d, d_WeffK0, nullptr, d_WK0, 128, 128, 128, b * 256 + tid);
    else if (b < 128)  mm_task(Wpre_d, d_WeffV0, nullptr, d_WV0, 128, 128, 128, (b - 64) * 256 + tid);
    else if (b < 192)  mm_task(Wpre_a, d_WeffK1, nullptr, d_WK1, 128, 128, 128, (b - 128) * 256 + tid);
    else if (b < 256)  mm_task(Wpre_a, d_WeffV1, nullptr, d_WV1, 128, 128, 128, (b - 192) * 256 + tid);
    else if (b < 384)  mm_task(Wpre_m, Wq, nullptr, d_Wqf, 256, 128, 128, (b - 256) * 256 + tid);
    else if (b == 384) mm_task(bpre + 128, d_WeffK0, d_beffK0, d_bK0, 1, 128, 128, tid);
    else if (b == 385) mm_task(bpre + 128, d_WeffV0, d_beffV0, d_bV0, 1, 128, 128, tid);
    else if (b == 386) mm_task(bpre + 256, d_WeffK1, d_beffK1, d_bK1, 1, 128, 128, tid);
    else if (b == 387) mm_task(bpre + 256, d_WeffV1, d_beffV1, d_bV1, 1, 128, 128, tid);
    else if (b == 388) mm_task(bpre, Wq, bq, d_bqf, 1, 128, 128, tid);
    else if (b < 397)  mm_task(Wpre_m, Wlin, nullptr, d_Wsf, 256, 128, 8, (b - 389) * 256 + tid);
    else if (b == 397) mm_task(bpre, Wlin, nullptr, d_bsf, 1, 128, 8, tid);
    else if (b < 402)  mm_task(Wa, Wlin, nullptr, d_Wcomb, 128, 128, 8, (b - 398) * 256 + tid);
    else               mm_task(ba, Wlin, nullptr, d_tmp8, 1, 128, 8, tid);
}

// ---------------- pipelined tf32 tensor-core GEMM ----------------
__device__ __forceinline__ void cpa16(void* s, const void* g, int psz) {
    uint32_t sa = (uint32_t)__cvta_generic_to_shared(s);
    asm volatile("cp.async.cg.shared.global [%0], [%1], 16, %2;" :: "r"(sa), "l"(g), "r"(psz));
}

template<int KT, bool FS0, bool HOUT>
__device__ __forceinline__ void gemm_body(const float* __restrict__ A, const float* __restrict__ W,
                                          const float* __restrict__ bias, void* __restrict__ Cv,
                                          int M, int row0,
                                          const float* __restrict__ Wsf, const float* __restrict__ bsf,
                                          float* __restrict__ S) {
    extern __shared__ float smem[];
    float* AsBase = smem;                 // 2 * 128 * 36 = 9216
    float* BsBase = smem + 9216;          // 2 * 32 * 136 = 8704
    float* sWs    = smem + 9216 + 8704;   // 2048

    const int K = KT * 32;
    int tid = threadIdx.x;
    int warp = tid >> 5, lane = tid & 31;
    int wm = warp >> 1, wn = warp & 1;
    int g = lane >> 2, tg = lane & 3;

    if (FS0) {
        for (int i = tid; i < 2048; i += 256) sWs[i] = Wsf[i];
    }

    float acc[2][8][4];
#pragma unroll
    for (int mi = 0; mi < 2; mi++)
#pragma unroll
        for (int ni = 0; ni < 8; ni++)
#pragma unroll
            for (int c = 0; c < 4; c++) acc[mi][ni][c] = 0.f;
    float sacc[4] = {0.f, 0.f, 0.f, 0.f};

    auto load_tile = [&](int kt, int buf) {
        float* Ab = AsBase + buf * (128 * 36);
        float* Bb = BsBase + buf * (32 * 136);
#pragma unroll
        for (int l = 0; l < 4; l++) {
            int cidx = tid + l * 256;
            int r = cidx >> 3, q = cidx & 7;
            int gr = row0 + r;
            const float* ga = (gr < M) ? &A[(size_t)gr * K + kt * 32 + q * 4] : A;
            cpa16(&Ab[r * 36 + q * 4], ga, (gr < M) ? 16 : 0);
        }
#pragma unroll
        for (int l = 0; l < 4; l++) {
            int cidx = tid + l * 256;
            int k = cidx >> 5, q = cidx & 31;
            cpa16(&Bb[k * 136 + q * 4], &W[(size_t)(kt * 32 + k) * 128 + q * 4], 16);
        }
        asm volatile("cp.async.commit_group;");
    };

    load_tile(0, 0);

    for (int t = 0; t < KT; t++) {
        if (t + 1 < KT) {
            load_tile(t + 1, (t + 1) & 1);
            asm volatile("cp.async.wait_group 1;");
        } else {
            asm volatile("cp.async.wait_group 0;");
        }
        __syncthreads();

        float* Ab = AsBase + (t & 1) * (128 * 36);
        float* Bb = BsBase + (t & 1) * (32 * 136);

#pragma unroll
        for (int ks = 0; ks < 32; ks += 8) {
            uint32_t a_[2][4];
#pragma unroll
            for (int mi = 0; mi < 2; mi++) {
                int ar = wm * 32 + mi * 16 + g;
                a_[mi][0] = __float_as_uint(Ab[ar * 36 + ks + tg]);
                a_[mi][1] = __float_as_uint(Ab[(ar + 8) * 36 + ks + tg]);
                a_[mi][2] = __float_as_uint(Ab[ar * 36 + ks + tg + 4]);
                a_[mi][3] = __float_as_uint(Ab[(ar + 8) * 36 + ks + tg + 4]);
            }
#pragma unroll
            for (int ni = 0; ni < 8; ni++) {
                int bc = wn * 64 + ni * 8 + g;
                uint32_t b0 = __float_as_uint(Bb[(ks + tg) * 136 + bc]);
                uint32_t b1 = __float_as_uint(Bb[(ks + tg + 4) * 136 + bc]);
#pragma unroll
                for (int mi = 0; mi < 2; mi++) {
                    asm volatile(
                        "mma.sync.aligned.m16n8k8.row.col.f32.tf32.tf32.f32 "
                        "{%0,%1,%2,%3}, {%4,%5,%6,%7}, {%8,%9}, {%0,%1,%2,%3};"
                        : "+f"(acc[mi][ni][0]), "+f"(acc[mi][ni][1]),
                          "+f"(acc[mi][ni][2]), "+f"(acc[mi][ni][3])
                        : "r"(a_[mi][0]), "r"(a_[mi][1]), "r"(a_[mi][2]), "r"(a_[mi][3]),
                          "r"(b0), "r"(b1));
                }
            }
        }

        if (FS0) {
            int r = tid >> 1, cg4 = (tid & 1) * 4;
            const float* Ar = &Ab[r * 36];
            const float* Wr = &sWs[t * 32 * 8 + cg4];
#pragma unroll
            for (int kk = 0; kk < 32; kk++) {
                float av = Ar[kk];
                float4 w = *(const float4*)&Wr[kk * 8];
                sacc[0] += av * w.x; sacc[1] += av * w.y;
                sacc[2] += av * w.z; sacc[3] += av * w.w;
            }
        }
        __syncthreads();
    }

#pragma unroll
    for (int mi = 0; mi < 2; mi++) {
#pragma unroll
        for (int ni = 0; ni < 8; ni++) {
            int col = wn * 64 + ni * 8 + tg * 2;
            float bx = bias[col], by = bias[col + 1];
            int r1 = row0 + wm * 32 + mi * 16 + g;
            int r2 = r1 + 8;
            if (HOUT) {
                __half* C = (__half*)Cv;
                if (r1 < M)
                    *(__half2*)&C[(size_t)r1 * 128 + col] =
                        __floats2half2_rn(acc[mi][ni][0] + bx, acc[mi][ni][1] + by);
                if (r2 < M)
                    *(__half2*)&C[(size_t)r2 * 128 + col] =
                        __floats2half2_rn(acc[mi][ni][2] + bx, acc[mi][ni][3] + by);
            } else {
                float* C = (float*)Cv;
                if (r1 < M) {
                    float2 o = make_float2(acc[mi][ni][0] + bx, acc[mi][ni][1] + by);
                    *(float2*)&C[(size_t)r1 * 128 + col] = o;
                }
                if (r2 < M) {
                    float2 o = make_float2(acc[mi][ni][2] + bx, acc[mi][ni][3] + by);
                    *(float2*)&C[(size_t)r2 * 128 + col] = o;
                }
            }
        }
    }

    if (FS0) {
        int r = tid >> 1, cg4 = (tid & 1) * 4;
        int gr = row0 + r;
        if (gr < M) {
            float4 o;
            o.x = sacc[0] + bsf[cg4 + 0];
            o.y = sacc[1] + bsf[cg4 + 1];
            o.z = sacc[2] + bsf[cg4 + 2];
            o.w = sacc[3] + bsf[cg4 + 3];
            *(float4*)&S[(size_t)gr * 8 + cg4] = o;
        }
    }
}

// single merged GEMM launch: q0 (fp16 out + fused s0, K=256) + 4 K/V GEMMs (K=128, fp16 out)
__global__ __launch_bounds__(256, 2)
void gemm_all(const float* __restrict__ x_m, const float* __restrict__ x_d,
              const float* __restrict__ x_a) {
    int b = blockIdx.x;
    if (b < 782) {
        gemm_body<8, true, true>(x_m, d_Wqf, d_bqf, d_q0h, NM, b * 128, d_Wsf, d_bsf, d_s0);
        return;
    }
    b -= 782;
    if (b < 157)      gemm_body<4, false, true>(x_d, d_WK0, d_bK0, d_ktdm, ND, b * 128, nullptr, nullptr, nullptr);
    else if (b < 314) gemm_body<4, false, true>(x_d, d_WV0, d_bV0, d_mtdm, ND, (b - 157) * 128, nullptr, nullptr, nullptr);
    else if (b < 705) gemm_body<4, false, true>(x_a, d_WK1, d_bK1, d_ktam, NA, (b - 314) * 128, nullptr, nullptr, nullptr);
    else              gemm_body<4, false, true>(x_a, d_WV1, d_bV1, d_mtam, NA, (b - 705) * 128, nullptr, nullptr, nullptr);
}

// ---------------- CSR build (counting sort by destination movie node) ----------------
__global__ void count_edges(const int* __restrict__ dst_dm, const int* __restrict__ dst_am) {
    int e = blockIdx.x * blockDim.x + threadIdx.x;
    if (e < E0) atomicAdd(&d_counts[dst_dm[e]], 1);
    else if (e < ETOT) atomicAdd(&d_counts[dst_am[e - E0]], 1);
}
__global__ void scan_block() {
    __shared__ int sh[1024];
    int i = blockIdx.x * 1024 + threadIdx.x;
    int v = (i < NM) ? d_counts[i] : 0;
    sh[threadIdx.x] = v;
    __syncthreads();
    for (int off = 1; off < 1024; off <<= 1) {
        int t = (threadIdx.x >= off) ? sh[threadIdx.x - off] : 0;
        __syncthreads();
        sh[threadIdx.x] += t;
        __syncthreads();
    }
    if (i < NM) d_rowptr[i] = sh[threadIdx.x] - v;
    if (threadIdx.x == 1023) d_bsum[blockIdx.x] = sh[1023];
}
__global__ void scan_bsum() {
    if (threadIdx.x == 0) {
        int s = 0;
        for (int b = 0; b < NB; b++) { int v = d_bsum[b]; d_bsum[b] = s; s += v; }
    }
}
__global__ void add_offsets() {
    int i = blockIdx.x * blockDim.x + threadIdx.x;
    if (i < NM) {
        int v = d_rowptr[i] + d_bsum[i >> 10];
        d_rowptr[i] = v;
        d_cursor[i] = v;
    }
    if (i == 0) d_rowptr[NM] = ETOT;
}
__global__ void fill_edges(const int* __restrict__ dst_dm, const int* __restrict__ dst_am,
                           const int* __restrict__ src_dm, const int* __restrict__ src_am) {
    int e = blockIdx.x * blockDim.x + threadIdx.x;
    int d, pay;
    if (e < E0)       { d = dst_dm[e];      pay = src_dm[e]; }
    else if (e < ETOT){ d = dst_am[e - E0]; pay = src_am[e - E0] | 0x80000000; }
    else return;
    int pos = atomicAdd(&d_cursor[d], 1);
    d_epay[pos] = pay;
}

// ---------------- fused: per-edge attention + softmax-agg + gelu + output head ----------------
__device__ __forceinline__ float gelu_exact(float x) { return x * normcdff(x); }

__device__ __forceinline__ float4 half8_to_f4(const __half* base, size_t off) {
    uint2 w = *(const uint2*)(base + off);
    float2 lo = __half22float2(*(__half2*)&w.x);
    float2 hi = __half22float2(*(__half2*)&w.y);
    return make_float4(lo.x, lo.y, hi.x, hi.y);
}

__global__ __launch_bounds__(256)
void agg_out(const float* __restrict__ p_rel, const float* __restrict__ skip,
             const float* __restrict__ blin, float* __restrict__ out) {
    __shared__ float sWc[128 * 8];
    __shared__ float sc[9];
    for (int i = threadIdx.x; i < 1024; i += 256) sWc[i] = d_Wcomb[i];
    if (threadIdx.x < 8) {
        float gg = 1.f / (1.f + expf(-skip[0]));
        sc[1 + threadIdx.x] = gg * d_tmp8[threadIdx.x] + blin[threadIdx.x];
        if (threadIdx.x == 0) sc[0] = gg;
    }
    __syncthreads();

    int warp = threadIdx.x >> 5, lane = threadIdx.x & 31;
    int node = blockIdx.x * 8 + warp;
    int h = lane >> 2;
    const float scale = 0.25f;
    float p0 = p_rel[h] * scale;
    float p1 = p_rel[8 + h] * scale;

    float4 qv = half8_to_f4(d_q0h, (size_t)node * 128 + lane * 4);
    int beg = d_rowptr[node], end = d_rowptr[node + 1];

    float4 acc = make_float4(0.f, 0.f, 0.f, 0.f);
    float den = 0.f;
    int i = beg;
    for (; i + 2 <= end; i += 2) {
        int pay0 = d_epay[i], pay1 = d_epay[i + 1];
        unsigned u0 = (unsigned)pay0, u1 = (unsigned)pay1;
        int src0 = pay0 & 0x7FFFFFFF, src1 = pay1 & 0x7FFFFFFF;
        const __half* kb0 = (u0 >> 31) ? d_ktam : d_ktdm;
        const __half* mb0 = (u0 >> 31) ? d_mtam : d_mtdm;
        const __half* kb1 = (u1 >> 31) ? d_ktam : d_ktdm;
        const __half* mb1 = (u1 >> 31) ? d_mtam : d_mtdm;
        float ph0 = (u0 >> 31) ? p1 : p0;
        float ph1 = (u1 >> 31) ? p1 : p0;
        size_t b0 = (size_t)src0 * 128 + lane * 4;
        size_t b1 = (size_t)src1 * 128 + lane * 4;
        float4 k0 = half8_to_f4(kb0, b0);
        float4 m0 = half8_to_f4(mb0, b0);
        float4 k1 = half8_to_f4(kb1, b1);
        float4 m1 = half8_to_f4(mb1, b1);
        float d0 = qv.x * k0.x + qv.y * k0.y + qv.z * k0.z + qv.w * k0.w;
        float d1 = qv.x * k1.x + qv.y * k1.y + qv.z * k1.z + qv.w * k1.w;
        d0 += __shfl_xor_sync(0xffffffffu, d0, 1);
        d1 += __shfl_xor_sync(0xffffffffu, d1, 1);
        d0 += __shfl_xor_sync(0xffffffffu, d0, 2);
        d1 += __shfl_xor_sync(0xffffffffu, d1, 2);
        float a0 = __expf(d0 * ph0);
        float a1 = __expf(d1 * ph1);
        den += a0 + a1;
        acc.x += a0 * m0.x + a1 * m1.x;
        acc.y += a0 * m0.y + a1 * m1.y;
        acc.z += a0 * m0.z + a1 * m1.z;
        acc.w += a0 * m0.w + a1 * m1.w;
    }
    if (i < end) {
        int pay = d_epay[i];
        unsigned u = (unsigned)pay;
        int src = pay & 0x7FFFFFFF;
        const __half* kb = (u >> 31) ? d_ktam : d_ktdm;
        const __half* mb = (u >> 31) ? d_mtam : d_mtdm;
        float ph = (u >> 31) ? p1 : p0;
        size_t b = (size_t)src * 128 + lane * 4;
        float4 k0 = half8_to_f4(kb, b);
        float4 m0 = half8_to_f4(mb, b);
        float d0 = qv.x * k0.x + qv.y * k0.y + qv.z * k0.z + qv.w * k0.w;
        d0 += __shfl_xor_sync(0xffffffffu, d0, 1);
        d0 += __shfl_xor_sync(0xffffffffu, d0, 2);
        float a0 = __expf(d0 * ph);
        den += a0;
        acc.x += a0 * m0.x; acc.y += a0 * m0.y;
        acc.z += a0 * m0.z; acc.w += a0 * m0.w;
    }

    float inv = (den > 0.f) ? (1.f / den) : 0.f;
    float gl[4];
    gl[0] = gelu_exact(acc.x * inv);
    gl[1] = gelu_exact(acc.y * inv);
    gl[2] = gelu_exact(acc.z * inv);
    gl[3] = gelu_exact(acc.w * inv);

    float o[8] = {0, 0, 0, 0, 0, 0, 0, 0};
    int r0 = lane * 4;
#pragma unroll
    for (int j = 0; j < 4; j++) {
        float gj = gl[j];
        const float* wr = &sWc[(r0 + j) * 8];
#pragma unroll
        for (int c = 0; c < 8; c++) o[c] += gj * wr[c];
    }
#pragma unroll
    for (int off = 16; off > 0; off >>= 1)
#pragma unroll
        for (int c = 0; c < 8; c++) o[c] += __shfl_xor_sync(0xffffffffu, o[c], off);

    if (lane == 0) {
        float g = sc[0];
        const float* s0p = &d_s0[(size_t)node * 8];
        float4 o1, o2;
        o1.x = g * o[0] + (1.f - g) * s0p[0] + sc[1];
        o1.y = g * o[1] + (1.f - g) * s0p[1] + sc[2];
        o1.z = g * o[2] + (1.f - g) * s0p[2] + sc[3];
        o1.w = g * o[3] + (1.f - g) * s0p[3] + sc[4];
        o2.x = g * o[4] + (1.f - g) * s0p[4] + sc[5];
        o2.y = g * o[5] + (1.f - g) * s0p[5] + sc[6];
        o2.z = g * o[6] + (1.f - g) * s0p[6] + sc[7];
        o2.w = g * o[7] + (1.f - g) * s0p[7] + sc[8];
        *(float4*)&out[(size_t)node * 8] = o1;
        *(float4*)&out[(size_t)node * 8 + 4] = o2;
    }
}

// ---------------- launch ----------------
#define SYM(p, s) cudaGetSymbolAddress((void**)&(p), s)

extern "C" void kernel_launch(void* const* d_in, const int* in_sizes, int n_in,
                              void* d_out, int out_size) {
    (void)in_sizes; (void)n_in; (void)out_size;
    const float* x_m   = (const float*)d_in[0];
    const float* x_d   = (const float*)d_in[1];
    const float* x_a   = (const float*)d_in[2];
    const int* src_dm  = (const int*)d_in[3];
    const int* dst_dm  = (const int*)d_in[4];
    const int* src_am  = (const int*)d_in[5];
    const int* dst_am  = (const int*)d_in[6];
    const float* Wpre_m = (const float*)d_in[11];
    const float* Wpre_d = (const float*)d_in[12];
    const float* Wpre_a = (const float*)d_in[13];
    const float* bpre   = (const float*)d_in[14];
    const float* Wk     = (const float*)d_in[15];
    const float* bk     = (const float*)d_in[16];
    const float* Wq     = (const float*)d_in[17];
    const float* bq     = (const float*)d_in[18];
    const float* Wv     = (const float*)d_in[19];
    const float* bv     = (const float*)d_in[20];
    const float* a_rel  = (const float*)d_in[21];
    const float* m_rel  = (const float*)d_in[22];
    const float* p_rel  = (const float*)d_in[23];
    const float* skip   = (const float*)d_in[24];
    const float* Wa     = (const float*)d_in[25];
    const float* ba     = (const float*)d_in[26];
    const float* Wlin   = (const float*)d_in[27];
    const float* blin   = (const float*)d_in[28];
    float* out = (float*)d_out;

    int* counts;
    SYM(counts, d_counts);

    const int SMEM_G = (9216 + 8704 + 2048) * 4;   // 79872 B
    static int attr_set = 0;
    if (!attr_set) {
        cudaFuncSetAttribute(gemm_all, cudaFuncAttributeMaxDynamicSharedMemorySize, SMEM_G);
        attr_set = 1;
    }

    // 1) weight prep + counts clear
    cudaMemsetAsync(counts, 0, NM * sizeof(int));
    prep_compose<<<516, 128>>>(Wk, bk, Wv, bv, a_rel, m_rel);
    prep_mm<<<403, 256>>>(Wpre_m, Wpre_d, Wpre_a, bpre, Wq, bq, Wa, ba, Wlin);

    // 2) CSR by destination movie node
    count_edges<<<2344, 256>>>(dst_dm, dst_am);
    scan_block<<<NB, 1024>>>();
    scan_bsum<<<1, 32>>>();
    add_offsets<<<391, 256>>>();
    fill_edges<<<2344, 256>>>(dst_dm, dst_am, src_dm, src_am);

    // 3) all node-level GEMMs in one launch (tf32 MMA; q0 + K/V all emit fp16)
    gemm_all<<<1878, 256, SMEM_G>>>(x_m, x_d, x_a);

    // 4) fused attention + softmax aggregation + gelu + output head
    agg_out<<<12500, 256>>>(p_rel, skip, blin, out);
}

// round 12
// speedup vs baseline: 1.0965x; 1.0458x over previous
#include <cuda_runtime.h>
#include <cuda_fp16.h>
#include <math.h>
#include <stdint.h>

#define NM 100000
#define ND 20000
#define NA 50000
#define E0 300000
#define ETOT 600000
#define NB 98   // ceil(NM/1024)

// ---------------- scratch (static device memory; no allocs) ----------------
__device__ __half d_q0h[NM * 128];
__device__ float  d_s0[NM * 8];
__device__ __half d_ktdm[ND * 128];
__device__ __half d_mtdm[ND * 128];
__device__ __half d_ktam[NA * 128];
__device__ __half d_mtam[NA * 128];
__device__ int    d_counts[NM];
__device__ int    d_cursor[NM];
__device__ int    d_rowptr[NM + 1];
__device__ int    d_bsum[128];
__device__ int    d_epay[ETOT];   // packed: src | (rel<<31)

__device__ float d_WeffK0[128 * 128], d_WeffV0[128 * 128];
__device__ float d_WeffK1[128 * 128], d_WeffV1[128 * 128];
__device__ float d_beffK0[128], d_beffV0[128], d_beffK1[128], d_beffV1[128];
__device__ float d_WK0[128 * 128], d_WV0[128 * 128], d_WK1[128 * 128], d_WV1[128 * 128];
__device__ float d_bK0[128], d_bV0[128], d_bK1[128], d_bV1[128];
__device__ float d_Wqf[256 * 128];
__device__ float d_bqf[128];
__device__ float d_Wsf[256 * 8];
__device__ float d_bsf[8];
__device__ float d_Wcomb[128 * 8];
__device__ float d_tmp8[8];

// ---------------- fused weight-composition kernels ----------------

__global__ void prep_compose(const float* __restrict__ Wk, const float* __restrict__ bk,
                             const float* __restrict__ Wv, const float* __restrict__ bv,
                             const float* __restrict__ a_rel, const float* __restrict__ m_rel) {
    int which = blockIdx.x / 129;
    int i = blockIdx.x - which * 129;
    const float *Win, *bin, *A; float *Weff, *beff;
    switch (which) {
        case 0: Win = Wk + 16384; bin = bk + 128; A = a_rel;        Weff = d_WeffK0; beff = d_beffK0; break;
        case 1: Win = Wk + 32768; bin = bk + 256; A = a_rel + 2048; Weff = d_WeffK1; beff = d_beffK1; break;
        case 2: Win = Wv + 16384; bin = bv + 128; A = m_rel;        Weff = d_WeffV0; beff = d_beffV0; break;
        default:Win = Wv + 32768; bin = bv + 256; A = m_rel + 2048; Weff = d_WeffV1; beff = d_beffV1; break;
    }
    int col = threadIdx.x;
    int h = col >> 4, f = col & 15;
    const float* arow = A + h * 256 + f;
    const float* w = (i < 128) ? (Win + i * 128 + h * 16) : (bin + h * 16);
    float s = 0.f;
#pragma unroll
    for (int d = 0; d < 16; d++) s += w[d] * arow[d * 16];
    if (i < 128) Weff[i * 128 + col] = s;
    else         beff[col] = s;
}

__device__ __forceinline__ void mm_task(const float* __restrict__ A, const float* __restrict__ B,
                                        const float* __restrict__ add, float* __restrict__ C,
                                        int M, int K, int N, int t) {
    if (t >= M * N) return;
    int m = t / N, n = t - m * N;
    float s = add ? add[n] : 0.f;
    for (int k = 0; k < K; k++) s += A[m * K + k] * B[k * N + n];
    C[t] = s;
}

__global__ void prep_mm(const float* __restrict__ Wpre_m, const float* __restrict__ Wpre_d,
                        const float* __restrict__ Wpre_a, const float* __restrict__ bpre,
                        const float* __restrict__ Wq, const float* __restrict__ bq,
                        const float* __restrict__ Wa, const float* __restrict__ ba,
                        const float* __restrict__ Wlin) {
    int b = blockIdx.x;
    int tid = threadIdx.x;
    if (b < 64)        mm_task(Wpre_d, d_WeffK0, nullptr, d_WK0, 128, 128, 128, b * 256 + tid);
    else if (b < 128)  mm_task(Wpre_d, d_WeffV0, nullptr, d_WV0, 128, 128, 128, (b - 64) * 256 + tid);
    else if (b < 192)  mm_task(Wpre_a, d_WeffK1, nullptr, d_WK1, 128, 128, 128, (b - 128) * 256 + tid);
    else if (b < 256)  mm_task(Wpre_a, d_WeffV1, nullptr, d_WV1, 128, 128, 128, (b - 192) * 256 + tid);
    else if (b < 384)  mm_task(Wpre_m, Wq, nullptr, d_Wqf, 256, 128, 128, (b - 256) * 256 + tid);
    else if (b == 384) mm_task(bpre + 128, d_WeffK0, d_beffK0, d_bK0, 1, 128, 128, tid);
    else if (b == 385) mm_task(bpre + 128, d_WeffV0, d_beffV0, d_bV0, 1, 128, 128, tid);
    else if (b == 386) mm_task(bpre + 256, d_WeffK1, d_beffK1, d_bK1, 1, 128, 128, tid);
    else if (b == 387) mm_task(bpre + 256, d_WeffV1, d_beffV1, d_bV1, 1, 128, 128, tid);
    else if (b == 388) mm_task(bpre, Wq, bq, d_bqf, 1, 128, 128, tid);
    else if (b < 397)  mm_task(Wpre_m, Wlin, nullptr, d_Wsf, 256, 128, 8, (b - 389) * 256 + tid);
    else if (b == 397) mm_task(bpre, Wlin, nullptr, d_bsf, 1, 128, 8, tid);
    else if (b < 402)  mm_task(Wa, Wlin, nullptr, d_Wcomb, 128, 128, 8, (b - 398) * 256 + tid);
    else               mm_task(ba, Wlin, nullptr, d_tmp8, 1, 128, 8, tid);
}

// ---------------- pipelined tf32 tensor-core GEMM ----------------
__device__ __forceinline__ void cpa16(void* s, const void* g, int psz) {
    uint32_t sa = (uint32_t)__cvta_generic_to_shared(s);
    asm volatile("cp.async.cg.shared.global [%0], [%1], 16, %2;" :: "r"(sa), "l"(g), "r"(psz));
}

template<int KT, bool FS0, bool HOUT>
__device__ __forceinline__ void gemm_body(const float* __restrict__ A, const float* __restrict__ W,
                                          const float* __restrict__ bias, void* __restrict__ Cv,
                                          int M, int row0,
                                          const float* __restrict__ Wsf, const float* __restrict__ bsf,
                                          float* __restrict__ S) {
    extern __shared__ float smem[];
    float* AsBase = smem;                 // 2 * 128 * 36 = 9216
    float* BsBase = smem + 9216;          // 2 * 32 * 136 = 8704
    float* sWs    = smem + 9216 + 8704;   // 2048

    const int K = KT * 32;
    int tid = threadIdx.x;
    int warp = tid >> 5, lane = tid & 31;
    int wm = warp >> 1, wn = warp & 1;
    int g = lane >> 2, tg = lane & 3;

    if (FS0) {
        for (int i = tid; i < 2048; i += 256) sWs[i] = Wsf[i];
    }

    float acc[2][8][4];
#pragma unroll
    for (int mi = 0; mi < 2; mi++)
#pragma unroll
        for (int ni = 0; ni < 8; ni++)
#pragma unroll
            for (int c = 0; c < 4; c++) acc[mi][ni][c] = 0.f;
    float sacc[4] = {0.f, 0.f, 0.f, 0.f};

    auto load_tile = [&](int kt, int buf) {
        float* Ab = AsBase + buf * (128 * 36);
        float* Bb = BsBase + buf * (32 * 136);
#pragma unroll
        for (int l = 0; l < 4; l++) {
            int cidx = tid + l * 256;
            int r = cidx >> 3, q = cidx & 7;
            int gr = row0 + r;
            const float* ga = (gr < M) ? &A[(size_t)gr * K + kt * 32 + q * 4] : A;
            cpa16(&Ab[r * 36 + q * 4], ga, (gr < M) ? 16 : 0);
        }
#pragma unroll
        for (int l = 0; l < 4; l++) {
            int cidx = tid + l * 256;
            int k = cidx >> 5, q = cidx & 31;
            cpa16(&Bb[k * 136 + q * 4], &W[(size_t)(kt * 32 + k) * 128 + q * 4], 16);
        }
        asm volatile("cp.async.commit_group;");
    };

    load_tile(0, 0);

    for (int t = 0; t < KT; t++) {
        if (t + 1 < KT) {
            load_tile(t + 1, (t + 1) & 1);
            asm volatile("cp.async.wait_group 1;");
        } else {
            asm volatile("cp.async.wait_group 0;");
        }
        __syncthreads();

        float* Ab = AsBase + (t & 1) * (128 * 36);
        float* Bb = BsBase + (t & 1) * (32 * 136);

#pragma unroll
        for (int ks = 0; ks < 32; ks += 8) {
            uint32_t a_[2][4];
#pragma unroll
            for (int mi = 0; mi < 2; mi++) {
                int ar = wm * 32 + mi * 16 + g;
                a_[mi][0] = __float_as_uint(Ab[ar * 36 + ks + tg]);
                a_[mi][1] = __float_as_uint(Ab[(ar + 8) * 36 + ks + tg]);
                a_[mi][2] = __float_as_uint(Ab[ar * 36 + ks + tg + 4]);
                a_[mi][3] = __float_as_uint(Ab[(ar + 8) * 36 + ks + tg + 4]);
            }
#pragma unroll
            for (int ni = 0; ni < 8; ni++) {
                int bc = wn * 64 + ni * 8 + g;
                uint32_t b0 = __float_as_uint(Bb[(ks + tg) * 136 + bc]);
                uint32_t b1 = __float_as_uint(Bb[(ks + tg + 4) * 136 + bc]);
#pragma unroll
                for (int mi = 0; mi < 2; mi++) {
                    asm volatile(
                        "mma.sync.aligned.m16n8k8.row.col.f32.tf32.tf32.f32 "
                        "{%0,%1,%2,%3}, {%4,%5,%6,%7}, {%8,%9}, {%0,%1,%2,%3};"
                        : "+f"(acc[mi][ni][0]), "+f"(acc[mi][ni][1]),
                          "+f"(acc[mi][ni][2]), "+f"(acc[mi][ni][3])
                        : "r"(a_[mi][0]), "r"(a_[mi][1]), "r"(a_[mi][2]), "r"(a_[mi][3]),
                          "r"(b0), "r"(b1));
                }
            }
        }

        if (FS0) {
            int r = tid >> 1, cg4 = (tid & 1) * 4;
            const float* Ar = &Ab[r * 36];
            const float* Wr = &sWs[t * 32 * 8 + cg4];
#pragma unroll
            for (int kk = 0; kk < 32; kk++) {
                float av = Ar[kk];
                float4 w = *(const float4*)&Wr[kk * 8];
                sacc[0] += av * w.x; sacc[1] += av * w.y;
                sacc[2] += av * w.z; sacc[3] += av * w.w;
            }
        }
        __syncthreads();
    }

#pragma unroll
    for (int mi = 0; mi < 2; mi++) {
#pragma unroll
        for (int ni = 0; ni < 8; ni++) {
            int col = wn * 64 + ni * 8 + tg * 2;
            float bx = bias[col], by = bias[col + 1];
            int r1 = row0 + wm * 32 + mi * 16 + g;
            int r2 = r1 + 8;
            if (HOUT) {
                __half* C = (__half*)Cv;
                if (r1 < M)
                    *(__half2*)&C[(size_t)r1 * 128 + col] =
                        __floats2half2_rn(acc[mi][ni][0] + bx, acc[mi][ni][1] + by);
                if (r2 < M)
                    *(__half2*)&C[(size_t)r2 * 128 + col] =
                        __floats2half2_rn(acc[mi][ni][2] + bx, acc[mi][ni][3] + by);
            } else {
                float* C = (float*)Cv;
                if (r1 < M) {
                    float2 o = make_float2(acc[mi][ni][0] + bx, acc[mi][ni][1] + by);
                    *(float2*)&C[(size_t)r1 * 128 + col] = o;
                }
                if (r2 < M) {
                    float2 o = make_float2(acc[mi][ni][2] + bx, acc[mi][ni][3] + by);
                    *(float2*)&C[(size_t)r2 * 128 + col] = o;
                }
            }
        }
    }

    if (FS0) {
        int r = tid >> 1, cg4 = (tid & 1) * 4;
        int gr = row0 + r;
        if (gr < M) {
            float4 o;
            o.x = sacc[0] + bsf[cg4 + 0];
            o.y = sacc[1] + bsf[cg4 + 1];
            o.z = sacc[2] + bsf[cg4 + 2];
            o.w = sacc[3] + bsf[cg4 + 3];
            *(float4*)&S[(size_t)gr * 8 + cg4] = o;
        }
    }
}

// single merged GEMM launch: q0 (fp16 out + fused s0, K=256) + 4 K/V GEMMs (K=128, fp16 out)
__global__ __launch_bounds__(256, 2)
void gemm_all(const float* __restrict__ x_m, const float* __restrict__ x_d,
              const float* __restrict__ x_a) {
    int b = blockIdx.x;
    if (b < 782) {
        gemm_body<8, true, true>(x_m, d_Wqf, d_bqf, d_q0h, NM, b * 128, d_Wsf, d_bsf, d_s0);
        return;
    }
    b -= 782;
    if (b < 157)      gemm_body<4, false, true>(x_d, d_WK0, d_bK0, d_ktdm, ND, b * 128, nullptr, nullptr, nullptr);
    else if (b < 314) gemm_body<4, false, true>(x_d, d_WV0, d_bV0, d_mtdm, ND, (b - 157) * 128, nullptr, nullptr, nullptr);
    else if (b < 705) gemm_body<4, false, true>(x_a, d_WK1, d_bK1, d_ktam, NA, (b - 314) * 128, nullptr, nullptr, nullptr);
    else              gemm_body<4, false, true>(x_a, d_WV1, d_bV1, d_mtam, NA, (b - 705) * 128, nullptr, nullptr, nullptr);
}

// ---------------- CSR build (counting sort by destination movie node) ----------------
__global__ void count_edges(const int* __restrict__ dst_dm, const int* __restrict__ dst_am) {
    int e = blockIdx.x * blockDim.x + threadIdx.x;
    if (e < E0) atomicAdd(&d_counts[dst_dm[e]], 1);
    else if (e < ETOT) atomicAdd(&d_counts[dst_am[e - E0]], 1);
}
__global__ void scan_block() {
    __shared__ int sh[1024];
    int i = blockIdx.x * 1024 + threadIdx.x;
    int v = (i < NM) ? d_counts[i] : 0;
    sh[threadIdx.x] = v;
    __syncthreads();
    for (int off = 1; off < 1024; off <<= 1) {
        int t = (threadIdx.x >= off) ? sh[threadIdx.x - off] : 0;
        __syncthreads();
        sh[threadIdx.x] += t;
        __syncthreads();
    }
    if (i < NM) d_rowptr[i] = sh[threadIdx.x] - v;
    if (threadIdx.x == 1023) d_bsum[blockIdx.x] = sh[1023];
}
__global__ void scan_bsum() {
    if (threadIdx.x == 0) {
        int s = 0;
        for (int b = 0; b < NB; b++) { int v = d_bsum[b]; d_bsum[b] = s; s += v; }
    }
}
__global__ void add_offsets() {
    int i = blockIdx.x * blockDim.x + threadIdx.x;
    if (i < NM) {
        int v = d_rowptr[i] + d_bsum[i >> 10];
        d_rowptr[i] = v;
        d_cursor[i] = v;
    }
    if (i == 0) d_rowptr[NM] = ETOT;
}
__global__ void fill_edges(const int* __restrict__ dst_dm, const int* __restrict__ dst_am,
                           const int* __restrict__ src_dm, const int* __restrict__ src_am) {
    int e = blockIdx.x * blockDim.x + threadIdx.x;
    int d, pay;
    if (e < E0)       { d = dst_dm[e];      pay = src_dm[e]; }
    else if (e < ETOT){ d = dst_am[e - E0]; pay = src_am[e - E0] | 0x80000000; }
    else return;
    int pos = atomicAdd(&d_cursor[d], 1);
    d_epay[pos] = pay;
}

// ---------------- fused: per-edge attention + softmax-agg + gelu + output head ----------------
__device__ __forceinline__ float gelu_exact(float x) { return x * normcdff(x); }

__device__ __forceinline__ float4 half8_to_f4(const __half* base, size_t off) {
    uint2 w = *(const uint2*)(base + off);
    float2 lo = __half22float2(*(__half2*)&w.x);
    float2 hi = __half22float2(*(__half2*)&w.y);
    return make_float4(lo.x, lo.y, hi.x, hi.y);
}

__global__ __launch_bounds__(256)
void agg_out(const float* __restrict__ p_rel, const float* __restrict__ skip,
             const float* __restrict__ blin, float* __restrict__ out) {
    __shared__ float sWc[128 * 8];
    __shared__ float sc[9];
    for (int i = threadIdx.x; i < 1024; i += 256) sWc[i] = d_Wcomb[i];
    if (threadIdx.x < 8) {
        float gg = 1.f / (1.f + expf(-skip[0]));
        sc[1 + threadIdx.x] = gg * d_tmp8[threadIdx.x] + blin[threadIdx.x];
        if (threadIdx.x == 0) sc[0] = gg;
    }
    __syncthreads();

    int warp = threadIdx.x >> 5, lane = threadIdx.x & 31;
    int node = blockIdx.x * 8 + warp;
    int h = lane >> 2;
    const float scale = 0.25f;
    float p0 = p_rel[h] * scale;
    float p1 = p_rel[8 + h] * scale;

    float4 qv = half8_to_f4(d_q0h, (size_t)node * 128 + lane * 4);
    int beg = d_rowptr[node], end = d_rowptr[node + 1];

    float4 acc = make_float4(0.f, 0.f, 0.f, 0.f);
    float den = 0.f;
    int i = beg;
    for (; i + 2 <= end; i += 2) {
        int pay0 = d_epay[i], pay1 = d_epay[i + 1];
        unsigned u0 = (unsigned)pay0, u1 = (unsigned)pay1;
        int src0 = pay0 & 0x7FFFFFFF, src1 = pay1 & 0x7FFFFFFF;
        const __half* kb0 = (u0 >> 31) ? d_ktam : d_ktdm;
        const __half* mb0 = (u0 >> 31) ? d_mtam : d_mtdm;
        const __half* kb1 = (u1 >> 31) ? d_ktam : d_ktdm;
        const __half* mb1 = (u1 >> 31) ? d_mtam : d_mtdm;
        float ph0 = (u0 >> 31) ? p1 : p0;
        float ph1 = (u1 >> 31) ? p1 : p0;
        size_t b0 = (size_t)src0 * 128 + lane * 4;
        size_t b1 = (size_t)src1 * 128 + lane * 4;
        float4 k0 = half8_to_f4(kb0, b0);
        float4 m0 = half8_to_f4(mb0, b0);
        float4 k1 = half8_to_f4(kb1, b1);
        float4 m1 = half8_to_f4(mb1, b1);
        float d0 = qv.x * k0.x + qv.y * k0.y + qv.z * k0.z + qv.w * k0.w;
        float d1 = qv.x * k1.x + qv.y * k1.y + qv.z * k1.z + qv.w * k1.w;
        d0 += __shfl_xor_sync(0xffffffffu, d0, 1);
        d1 += __shfl_xor_sync(0xffffffffu, d1, 1);
        d0 += __shfl_xor_sync(0xffffffffu, d0, 2);
        d1 += __shfl_xor_sync(0xffffffffu, d1, 2);
        float a0 = __expf(d0 * ph0);
        float a1 = __expf(d1 * ph1);
        den += a0 + a1;
        acc.x += a0 * m0.x + a1 * m1.x;
        acc.y += a0 * m0.y + a1 * m1.y;
        acc.z += a0 * m0.z + a1 * m1.z;
        acc.w += a0 * m0.w + a1 * m1.w;
    }
    if (i < end) {
        int pay = d_epay[i];
        unsigned u = (unsigned)pay;
        int src = pay & 0x7FFFFFFF;
        const __half* kb = (u >> 31) ? d_ktam : d_ktdm;
        const __half* mb = (u >> 31) ? d_mtam : d_mtdm;
        float ph = (u >> 31) ? p1 : p0;
        size_t b = (size_t)src * 128 + lane * 4;
        float4 k0 = half8_to_f4(kb, b);
        float4 m0 = half8_to_f4(mb, b);
        float d0 = qv.x * k0.x + qv.y * k0.y + qv.z * k0.z + qv.w * k0.w;
        d0 += __shfl_xor_sync(0xffffffffu, d0, 1);
        d0 += __shfl_xor_sync(0xffffffffu, d0, 2);
        float a0 = __expf(d0 * ph);
        den += a0;
        acc.x += a0 * m0.x; acc.y += a0 * m0.y;
        acc.z += a0 * m0.z; acc.w += a0 * m0.w;
    }

    float inv = (den > 0.f) ? (1.f / den) : 0.f;
    float gl[4];
    gl[0] = gelu_exact(acc.x * inv);
    gl[1] = gelu_exact(acc.y * inv);
    gl[2] = gelu_exact(acc.z * inv);
    gl[3] = gelu_exact(acc.w * inv);

    float o[8] = {0, 0, 0, 0, 0, 0, 0, 0};
    int r0 = lane * 4;
#pragma unroll
    for (int j = 0; j < 4; j++) {
        float gj = gl[j];
        const float* wr = &sWc[(r0 + j) * 8];
#pragma unroll
        for (int c = 0; c < 8; c++) o[c] += gj * wr[c];
    }
#pragma unroll
    for (int off = 16; off > 0; off >>= 1)
#pragma unroll
        for (int c = 0; c < 8; c++) o[c] += __shfl_xor_sync(0xffffffffu, o[c], off);

    if (lane == 0) {
        float g = sc[0];
        const float* s0p = &d_s0[(size_t)node * 8];
        float4 o1, o2;
        o1.x = g * o[0] + (1.f - g) * s0p[0] + sc[1];
        o1.y = g * o[1] + (1.f - g) * s0p[1] + sc[2];
        o1.z = g * o[2] + (1.f - g) * s0p[2] + sc[3];
        o1.w = g * o[3] + (1.f - g) * s0p[3] + sc[4];
        o2.x = g * o[4] + (1.f - g) * s0p[4] + sc[5];
        o2.y = g * o[5] + (1.f - g) * s0p[5] + sc[6];
        o2.z = g * o[6] + (1.f - g) * s0p[6] + sc[7];
        o2.w = g * o[7] + (1.f - g) * s0p[7] + sc[8];
        *(float4*)&out[(size_t)node * 8] = o1;
        *(float4*)&out[(size_t)node * 8 + 4] = o2;
    }
}

// ---------------- launch ----------------
#define SYM(p, s) cudaGetSymbolAddress((void**)&(p), s)

extern "C" void kernel_launch(void* const* d_in, const int* in_sizes, int n_in,
                              void* d_out, int out_size) {
    (void)in_sizes; (void)n_in; (void)out_size;
    const float* x_m   = (const float*)d_in[0];
    const float* x_d   = (const float*)d_in[1];
    const float* x_a   = (const float*)d_in[2];
    const int* src_dm  = (const int*)d_in[3];
    const int* dst_dm  = (const int*)d_in[4];
    const int* src_am  = (const int*)d_in[5];
    const int* dst_am  = (const int*)d_in[6];
    const float* Wpre_m = (const float*)d_in[11];
    const float* Wpre_d = (const float*)d_in[12];
    const float* Wpre_a = (const float*)d_in[13];
    const float* bpre   = (const float*)d_in[14];
    const float* Wk     = (const float*)d_in[15];
    const float* bk     = (const float*)d_in[16];
    const float* Wq     = (const float*)d_in[17];
    const float* bq     = (const float*)d_in[18];
    const float* Wv     = (const float*)d_in[19];
    const float* bv     = (const float*)d_in[20];
    const float* a_rel  = (const float*)d_in[21];
    const float* m_rel  = (const float*)d_in[22];
    const float* p_rel  = (const float*)d_in[23];
    const float* skip   = (const float*)d_in[24];
    const float* Wa     = (const float*)d_in[25];
    const float* ba     = (const float*)d_in[26];
    const float* Wlin   = (const float*)d_in[27];
    const float* blin   = (const float*)d_in[28];
    float* out = (float*)d_out;

    int* counts;
    SYM(counts, d_counts);

    const int SMEM_G = (9216 + 8704 + 2048) * 4;   // 79872 B

    // lazy one-time setup (runs on the first, non-captured, correctness call)
    static cudaStream_t s2 = nullptr;
    static cudaEvent_t evFork = nullptr, evJoin = nullptr;
    if (!s2) {
        cudaFuncSetAttribute(gemm_all, cudaFuncAttributeMaxDynamicSharedMemorySize, SMEM_G);
        cudaStreamCreateWithFlags(&s2, cudaStreamNonBlocking);
        cudaEventCreateWithFlags(&evFork, cudaEventDisableTiming);
        cudaEventCreateWithFlags(&evJoin, cudaEventDisableTiming);
    }

    // ---- fork: CSR build on side stream, overlapped with weight prep + GEMMs ----
    cudaEventRecord(evFork, 0);
    cudaStreamWaitEvent(s2, evFork, 0);

    // branch B (s2): CSR by destination movie node
    cudaMemsetAsync(counts, 0, NM * sizeof(int), s2);
    count_edges<<<2344, 256, 0, s2>>>(dst_dm, dst_am);
    scan_block<<<NB, 1024, 0, s2>>>();
    scan_bsum<<<1, 32, 0, s2>>>();
    add_offsets<<<391, 256, 0, s2>>>();
    fill_edges<<<2344, 256, 0, s2>>>(dst_dm, dst_am, src_dm, src_am);
    cudaEventRecord(evJoin, s2);

    // branch A (stream 0): weight prep + all node-level GEMMs
    prep_compose<<<516, 128>>>(Wk, bk, Wv, bv, a_rel, m_rel);
    prep_mm<<<403, 256>>>(Wpre_m, Wpre_d, Wpre_a, bpre, Wq, bq, Wa, ba, Wlin);
    gemm_all<<<1878, 256, SMEM_G>>>(x_m, x_d, x_a);

    // ---- join: attention aggregation needs both branches ----
    cudaStreamWaitEvent(0, evJoin, 0);
    agg_out<<<12500, 256>>>(p_rel, skip, blin, out);
}

// round 13
// speedup vs baseline: 1.1303x; 1.0308x over previous
#include <cuda_runtime.h>
#include <cuda_fp16.h>
#include <math.h>
#include <stdint.h>

#define NM 100000
#define ND 20000
#define NA 50000
#define E0 300000
#define ETOT 600000
#define NB 98   // ceil(NM/1024)

// ---------------- scratch (static device memory; no allocs) ----------------
__device__ __half d_q0h[NM * 128];
__device__ float  d_s0[NM * 8];
__device__ __half d_ktdm[ND * 128];
__device__ __half d_mtdm[ND * 128];
__device__ __half d_ktam[NA * 128];
__device__ __half d_mtam[NA * 128];
__device__ int    d_counts[NM];
__device__ int    d_cursor[NM];
__device__ int    d_rowptr[NM + 1];
__device__ int    d_bsum[128];
__device__ int    d_epay[ETOT];   // packed: src | (rel<<31)

__device__ float d_WeffK0[128 * 128], d_WeffV0[128 * 128];
__device__ float d_WeffK1[128 * 128], d_WeffV1[128 * 128];
__device__ float d_beffK0[128], d_beffV0[128], d_beffK1[128], d_beffV1[128];
// fp16 transposed weights for the MMA GEMMs: Wt[n][k]
__device__ __half d_WqfT[128 * 256];
__device__ __half d_WK0T[128 * 128], d_WV0T[128 * 128];
__device__ __half d_WK1T[128 * 128], d_WV1T[128 * 128];
__device__ float d_bK0[128], d_bV0[128], d_bK1[128], d_bV1[128];
__device__ float d_bqf[128];
__device__ float d_Wsf[256 * 8];
__device__ float d_bsf[8];
__device__ float d_Wcomb[128 * 8];
__device__ float d_tmp8[8];

// ---------------- fused weight-composition kernels ----------------

__global__ void prep_compose(const float* __restrict__ Wk, const float* __restrict__ bk,
                             const float* __restrict__ Wv, const float* __restrict__ bv,
                             const float* __restrict__ a_rel, const float* __restrict__ m_rel) {
    int which = blockIdx.x / 129;
    int i = blockIdx.x - which * 129;
    const float *Win, *bin, *A; float *Weff, *beff;
    switch (which) {
        case 0: Win = Wk + 16384; bin = bk + 128; A = a_rel;        Weff = d_WeffK0; beff = d_beffK0; break;
        case 1: Win = Wk + 32768; bin = bk + 256; A = a_rel + 2048; Weff = d_WeffK1; beff = d_beffK1; break;
        case 2: Win = Wv + 16384; bin = bv + 128; A = m_rel;        Weff = d_WeffV0; beff = d_beffV0; break;
        default:Win = Wv + 32768; bin = bv + 256; A = m_rel + 2048; Weff = d_WeffV1; beff = d_beffV1; break;
    }
    int col = threadIdx.x;
    int h = col >> 4, f = col & 15;
    const float* arow = A + h * 256 + f;
    const float* w = (i < 128) ? (Win + i * 128 + h * 16) : (bin + h * 16);
    float s = 0.f;
#pragma unroll
    for (int d = 0; d < 16; d++) s += w[d] * arow[d * 16];
    if (i < 128) Weff[i * 128 + col] = s;
    else         beff[col] = s;
}

// f32 output variant (biases + thin-GEMM weights)
__device__ __forceinline__ void mm_task(const float* __restrict__ A, const float* __restrict__ B,
                                        const float* __restrict__ add, float* __restrict__ C,
                                        int M, int K, int N, int t) {
    if (t >= M * N) return;
    int m = t / N, n = t - m * N;
    float s = add ? add[n] : 0.f;
    for (int k = 0; k < K; k++) s += A[m * K + k] * B[k * N + n];
    C[t] = s;
}

// fp16 TRANSPOSED output variant: Ct[n][m] = sum_k A[m][k] B[k][n]
__device__ __forceinline__ void mm_task_h(const float* __restrict__ A, const float* __restrict__ B,
                                          __half* __restrict__ Ct,
                                          int M, int K, int N, int t) {
    if (t >= M * N) return;
    int m = t / N, n = t - m * N;
    float s = 0.f;
    for (int k = 0; k < K; k++) s += A[m * K + k] * B[k * N + n];
    Ct[n * M + m] = __float2half_rn(s);
}

__global__ void prep_mm(const float* __restrict__ Wpre_m, const float* __restrict__ Wpre_d,
                        const float* __restrict__ Wpre_a, const float* __restrict__ bpre,
                        const float* __restrict__ Wq, const float* __restrict__ bq,
                        const float* __restrict__ Wa, const float* __restrict__ ba,
                        const float* __restrict__ Wlin) {
    int b = blockIdx.x;
    int tid = threadIdx.x;
    if (b < 64)        mm_task_h(Wpre_d, d_WeffK0, d_WK0T, 128, 128, 128, b * 256 + tid);
    else if (b < 128)  mm_task_h(Wpre_d, d_WeffV0, d_WV0T, 128, 128, 128, (b - 64) * 256 + tid);
    else if (b < 192)  mm_task_h(Wpre_a, d_WeffK1, d_WK1T, 128, 128, 128, (b - 128) * 256 + tid);
    else if (b < 256)  mm_task_h(Wpre_a, d_WeffV1, d_WV1T, 128, 128, 128, (b - 192) * 256 + tid);
    else if (b < 384)  mm_task_h(Wpre_m, Wq, d_WqfT, 256, 128, 128, (b - 256) * 256 + tid);
    else if (b == 384) mm_task(bpre + 128, d_WeffK0, d_beffK0, d_bK0, 1, 128, 128, tid);
    else if (b == 385) mm_task(bpre + 128, d_WeffV0, d_beffV0, d_bV0, 1, 128, 128, tid);
    else if (b == 386) mm_task(bpre + 256, d_WeffK1, d_beffK1, d_bK1, 1, 128, 128, tid);
    else if (b == 387) mm_task(bpre + 256, d_WeffV1, d_beffV1, d_bV1, 1, 128, 128, tid);
    else if (b == 388) mm_task(bpre, Wq, bq, d_bqf, 1, 128, 128, tid);
    else if (b < 397)  mm_task(Wpre_m, Wlin, nullptr, d_Wsf, 256, 128, 8, (b - 389) * 256 + tid);
    else if (b == 397) mm_task(bpre, Wlin, nullptr, d_bsf, 1, 128, 8, tid);
    else if (b < 402)  mm_task(Wa, Wlin, nullptr, d_Wcomb, 128, 128, 8, (b - 398) * 256 + tid);
    else               mm_task(ba, Wlin, nullptr, d_tmp8, 1, 128, 8, tid);
}

// ---------------- pipelined fp16 tensor-core GEMM ----------------
// C[M x 128] = A[M x K](f32) @ W[K x 128](fp16, stored transposed Wt[n][k]) + bias.
// 2-stage cp.async pipeline; A converted f32->fp16 at fragment load; mma.m16n8k16.
// smem bytes: As 2*128*36*4 = 36864 | Bst 2*128*40*2 = 20480 | sWs 2048*4 = 8192  => 65536

__device__ __forceinline__ void cpa16(void* s, const void* g, int psz) {
    uint32_t sa = (uint32_t)__cvta_generic_to_shared(s);
    asm volatile("cp.async.cg.shared.global [%0], [%1], 16, %2;" :: "r"(sa), "l"(g), "r"(psz));
}

template<int KT, bool FS0, bool HOUT>
__device__ __forceinline__ void gemm_body(const float* __restrict__ A, const __half* __restrict__ Wt,
                                          const float* __restrict__ bias, void* __restrict__ Cv,
                                          int M, int row0,
                                          const float* __restrict__ Wsf, const float* __restrict__ bsf,
                                          float* __restrict__ S) {
    extern __shared__ char smem_raw[];
    float*  AsBase = (float*)smem_raw;                    // 2 * 128 * 36 floats
    __half* BsBase = (__half*)(smem_raw + 36864);         // 2 * 128 * 40 halves
    float*  sWs    = (float*)(smem_raw + 36864 + 20480);  // 2048 floats

    const int K = KT * 32;
    int tid = threadIdx.x;
    int warp = tid >> 5, lane = tid & 31;
    int wm = warp >> 1, wn = warp & 1;
    int g = lane >> 2, tg = lane & 3;

    if (FS0) {
        for (int i = tid; i < 2048; i += 256) sWs[i] = Wsf[i];
    }

    float acc[2][8][4];
#pragma unroll
    for (int mi = 0; mi < 2; mi++)
#pragma unroll
        for (int ni = 0; ni < 8; ni++)
#pragma unroll
            for (int c = 0; c < 4; c++) acc[mi][ni][c] = 0.f;
    float sacc[4] = {0.f, 0.f, 0.f, 0.f};

    auto load_tile = [&](int kt, int buf) {
        float*  Ab = AsBase + buf * (128 * 36);
        __half* Bb = BsBase + buf * (128 * 40);
        // A tile: 128 rows x 32 k (f32)
#pragma unroll
        for (int l = 0; l < 4; l++) {
            int cidx = tid + l * 256;
            int r = cidx >> 3, q = cidx & 7;
            int gr = row0 + r;
            const float* ga = (gr < M) ? &A[(size_t)gr * K + kt * 32 + q * 4] : A;
            cpa16(&Ab[r * 36 + q * 4], ga, (gr < M) ? 16 : 0);
        }
        // W tile: 128 cols x 32 k (fp16, k-contiguous), smem stride 40 halves
#pragma unroll
        for (int l = 0; l < 2; l++) {
            int cidx = tid + l * 256;            // 0..511
            int col = cidx >> 2, q = (cidx & 3) * 8;
            cpa16(&Bb[col * 40 + q], &Wt[(size_t)col * K + kt * 32 + q], 16);
        }
        asm volatile("cp.async.commit_group;");
    };

    load_tile(0, 0);

    for (int t = 0; t < KT; t++) {
        if (t + 1 < KT) {
            load_tile(t + 1, (t + 1) & 1);
            asm volatile("cp.async.wait_group 1;");
        } else {
            asm volatile("cp.async.wait_group 0;");
        }
        __syncthreads();

        float*  Ab = AsBase + (t & 1) * (128 * 36);
        __half* Bb = BsBase + (t & 1) * (128 * 40);

#pragma unroll
        for (int ks = 0; ks < 32; ks += 16) {
            int c = ks + tg * 2;
            uint32_t a_[2][4];
#pragma unroll
            for (int mi = 0; mi < 2; mi++) {
                int ar = wm * 32 + mi * 16 + g;
                float2 v0 = *(const float2*)&Ab[ar * 36 + c];
                float2 v1 = *(const float2*)&Ab[(ar + 8) * 36 + c];
                float2 v2 = *(const float2*)&Ab[ar * 36 + c + 8];
                float2 v3 = *(const float2*)&Ab[(ar + 8) * 36 + c + 8];
                __half2 h0 = __floats2half2_rn(v0.x, v0.y);
                __half2 h1 = __floats2half2_rn(v1.x, v1.y);
                __half2 h2 = __floats2half2_rn(v2.x, v2.y);
                __half2 h3 = __floats2half2_rn(v3.x, v3.y);
                a_[mi][0] = *(uint32_t*)&h0;
                a_[mi][1] = *(uint32_t*)&h1;
                a_[mi][2] = *(uint32_t*)&h2;
                a_[mi][3] = *(uint32_t*)&h3;
            }
#pragma unroll
            for (int ni = 0; ni < 8; ni++) {
                int bc = wn * 64 + ni * 8 + g;
                uint32_t b0 = *(const uint32_t*)&Bb[bc * 40 + c];
                uint32_t b1 = *(const uint32_t*)&Bb[bc * 40 + c + 8];
#pragma unroll
                for (int mi = 0; mi < 2; mi++) {
                    asm volatile(
                        "mma.sync.aligned.m16n8k16.row.col.f32.f16.f16.f32 "
                        "{%0,%1,%2,%3}, {%4,%5,%6,%7}, {%8,%9}, {%0,%1,%2,%3};"
                        : "+f"(acc[mi][ni][0]), "+f"(acc[mi][ni][1]),
                          "+f"(acc[mi][ni][2]), "+f"(acc[mi][ni][3])
                        : "r"(a_[mi][0]), "r"(a_[mi][1]), "r"(a_[mi][2]), "r"(a_[mi][3]),
                          "r"(b0), "r"(b1));
                }
            }
        }

        if (FS0) {
            int r = tid >> 1, cg4 = (tid & 1) * 4;
            const float* Ar = &Ab[r * 36];
            const float* Wr = &sWs[t * 32 * 8 + cg4];
#pragma unroll
            for (int kk = 0; kk < 32; kk++) {
                float av = Ar[kk];
                float4 w = *(const float4*)&Wr[kk * 8];
                sacc[0] += av * w.x; sacc[1] += av * w.y;
                sacc[2] += av * w.z; sacc[3] += av * w.w;
            }
        }
        __syncthreads();
    }

#pragma unroll
    for (int mi = 0; mi < 2; mi++) {
#pragma unroll
        for (int ni = 0; ni < 8; ni++) {
            int col = wn * 64 + ni * 8 + tg * 2;
            float bx = bias[col], by = bias[col + 1];
            int r1 = row0 + wm * 32 + mi * 16 + g;
            int r2 = r1 + 8;
            if (HOUT) {
                __half* C = (__half*)Cv;
                if (r1 < M)
                    *(__half2*)&C[(size_t)r1 * 128 + col] =
                        __floats2half2_rn(acc[mi][ni][0] + bx, acc[mi][ni][1] + by);
                if (r2 < M)
                    *(__half2*)&C[(size_t)r2 * 128 + col] =
                        __floats2half2_rn(acc[mi][ni][2] + bx, acc[mi][ni][3] + by);
            } else {
                float* C = (float*)Cv;
                if (r1 < M) {
                    float2 o = make_float2(acc[mi][ni][0] + bx, acc[mi][ni][1] + by);
                    *(float2*)&C[(size_t)r1 * 128 + col] = o;
                }
                if (r2 < M) {
                    float2 o = make_float2(acc[mi][ni][2] + bx, acc[mi][ni][3] + by);
                    *(float2*)&C[(size_t)r2 * 128 + col] = o;
                }
            }
        }
    }

    if (FS0) {
        int r = tid >> 1, cg4 = (tid & 1) * 4;
        int gr = row0 + r;
        if (gr < M) {
            float4 o;
            o.x = sacc[0] + bsf[cg4 + 0];
            o.y = sacc[1] + bsf[cg4 + 1];
            o.z = sacc[2] + bsf[cg4 + 2];
            o.w = sacc[3] + bsf[cg4 + 3];
            *(float4*)&S[(size_t)gr * 8 + cg4] = o;
        }
    }
}

// single merged GEMM launch: q0 (fp16 out + fused s0, K=256) + 4 K/V GEMMs (K=128, fp16 out)
__global__ __launch_bounds__(256, 2)
void gemm_all(const float* __restrict__ x_m, const float* __restrict__ x_d,
              const float* __restrict__ x_a) {
    int b = blockIdx.x;
    if (b < 782) {
        gemm_body<8, true, true>(x_m, d_WqfT, d_bqf, d_q0h, NM, b * 128, d_Wsf, d_bsf, d_s0);
        return;
    }
    b -= 782;
    if (b < 157)      gemm_body<4, false, true>(x_d, d_WK0T, d_bK0, d_ktdm, ND, b * 128, nullptr, nullptr, nullptr);
    else if (b < 314) gemm_body<4, false, true>(x_d, d_WV0T, d_bV0, d_mtdm, ND, (b - 157) * 128, nullptr, nullptr, nullptr);
    else if (b < 705) gemm_body<4, false, true>(x_a, d_WK1T, d_bK1, d_ktam, NA, (b - 314) * 128, nullptr, nullptr, nullptr);
    else              gemm_body<4, false, true>(x_a, d_WV1T, d_bV1, d_mtam, NA, (b - 705) * 128, nullptr, nullptr, nullptr);
}

// ---------------- CSR build (counting sort by destination movie node) ----------------
__global__ void count_edges(const int* __restrict__ dst_dm, const int* __restrict__ dst_am) {
    int e = blockIdx.x * blockDim.x + threadIdx.x;
    if (e < E0) atomicAdd(&d_counts[dst_dm[e]], 1);
    else if (e < ETOT) atomicAdd(&d_counts[dst_am[e - E0]], 1);
}
__global__ void scan_block() {
    __shared__ int sh[1024];
    int i = blockIdx.x * 1024 + threadIdx.x;
    int v = (i < NM) ? d_counts[i] : 0;
    sh[threadIdx.x] = v;
    __syncthreads();
    for (int off = 1; off < 1024; off <<= 1) {
        int t = (threadIdx.x >= off) ? sh[threadIdx.x - off] : 0;
        __syncthreads();
        sh[threadIdx.x] += t;
        __syncthreads();
    }
    if (i < NM) d_rowptr[i] = sh[threadIdx.x] - v;
    if (threadIdx.x == 1023) d_bsum[blockIdx.x] = sh[1023];
}
__global__ void scan_bsum() {
    if (threadIdx.x == 0) {
        int s = 0;
        for (int b = 0; b < NB; b++) { int v = d_bsum[b]; d_bsum[b] = s; s += v; }
    }
}
__global__ void add_offsets() {
    int i = blockIdx.x * blockDim.x + threadIdx.x;
    if (i < NM) {
        int v = d_rowptr[i] + d_bsum[i >> 10];
        d_rowptr[i] = v;
        d_cursor[i] = v;
    }
    if (i == 0) d_rowptr[NM] = ETOT;
}
__global__ void fill_edges(const int* __restrict__ dst_dm, const int* __restrict__ dst_am,
                           const int* __restrict__ src_dm, const int* __restrict__ src_am) {
    int e = blockIdx.x * blockDim.x + threadIdx.x;
    int d, pay;
    if (e < E0)       { d = dst_dm[e];      pay = src_dm[e]; }
    else if (e < ETOT){ d = dst_am[e - E0]; pay = src_am[e - E0] | 0x80000000; }
    else return;
    int pos = atomicAdd(&d_cursor[d], 1);
    d_epay[pos] = pay;
}

// ---------------- fused: per-edge attention + softmax-agg + gelu + output head ----------------
__device__ __forceinline__ float gelu_exact(float x) { return x * normcdff(x); }

__device__ __forceinline__ float4 half8_to_f4(const __half* base, size_t off) {
    uint2 w = *(const uint2*)(base + off);
    float2 lo = __half22float2(*(__half2*)&w.x);
    float2 hi = __half22float2(*(__half2*)&w.y);
    return make_float4(lo.x, lo.y, hi.x, hi.y);
}

__global__ __launch_bounds__(256)
void agg_out(const float* __restrict__ p_rel, const float* __restrict__ skip,
             const float* __restrict__ blin, float* __restrict__ out) {
    __shared__ float sWc[128 * 8];
    __shared__ float sc[9];
    for (int i = threadIdx.x; i < 1024; i += 256) sWc[i] = d_Wcomb[i];
    if (threadIdx.x < 8) {
        float gg = 1.f / (1.f + expf(-skip[0]));
        sc[1 + threadIdx.x] = gg * d_tmp8[threadIdx.x] + blin[threadIdx.x];
        if (threadIdx.x == 0) sc[0] = gg;
    }
    __syncthreads();

    int warp = threadIdx.x >> 5, lane = threadIdx.x & 31;
    int node = blockIdx.x * 8 + warp;
    int h = lane >> 2;
    const float scale = 0.25f;
    float p0 = p_rel[h] * scale;
    float p1 = p_rel[8 + h] * scale;

    float4 qv = half8_to_f4(d_q0h, (size_t)node * 128 + lane * 4);
    int beg = d_rowptr[node], end = d_rowptr[node + 1];

    float4 acc = make_float4(0.f, 0.f, 0.f, 0.f);
    float den = 0.f;
    int i = beg;
    for (; i + 2 <= end; i += 2) {
        int pay0 = d_epay[i], pay1 = d_epay[i + 1];
        unsigned u0 = (unsigned)pay0, u1 = (unsigned)pay1;
        int src0 = pay0 & 0x7FFFFFFF, src1 = pay1 & 0x7FFFFFFF;
        const __half* kb0 = (u0 >> 31) ? d_ktam : d_ktdm;
        const __half* mb0 = (u0 >> 31) ? d_mtam : d_mtdm;
        const __half* kb1 = (u1 >> 31) ? d_ktam : d_ktdm;
        const __half* mb1 = (u1 >> 31) ? d_mtam : d_mtdm;
        float ph0 = (u0 >> 31) ? p1 : p0;
        float ph1 = (u1 >> 31) ? p1 : p0;
        size_t b0 = (size_t)src0 * 128 + lane * 4;
        size_t b1 = (size_t)src1 * 128 + lane * 4;
        float4 k0 = half8_to_f4(kb0, b0);
        float4 m0 = half8_to_f4(mb0, b0);
        float4 k1 = half8_to_f4(kb1, b1);
        float4 m1 = half8_to_f4(mb1, b1);
        float d0 = qv.x * k0.x + qv.y * k0.y + qv.z * k0.z + qv.w * k0.w;
        float d1 = qv.x * k1.x + qv.y * k1.y + qv.z * k1.z + qv.w * k1.w;
        d0 += __shfl_xor_sync(0xffffffffu, d0, 1);
        d1 += __shfl_xor_sync(0xffffffffu, d1, 1);
        d0 += __shfl_xor_sync(0xffffffffu, d0, 2);
        d1 += __shfl_xor_sync(0xffffffffu, d1, 2);
        float a0 = __expf(d0 * ph0);
        float a1 = __expf(d1 * ph1);
        den += a0 + a1;
        acc.x += a0 * m0.x + a1 * m1.x;
        acc.y += a0 * m0.y + a1 * m1.y;
        acc.z += a0 * m0.z + a1 * m1.z;
        acc.w += a0 * m0.w + a1 * m1.w;
    }
    if (i < end) {
        int pay = d_epay[i];
        unsigned u = (unsigned)pay;
        int src = pay & 0x7FFFFFFF;
        const __half* kb = (u >> 31) ? d_ktam : d_ktdm;
        const __half* mb = (u >> 31) ? d_mtam : d_mtdm;
        float ph = (u >> 31) ? p1 : p0;
        size_t b = (size_t)src * 128 + lane * 4;
        float4 k0 = half8_to_f4(kb, b);
        float4 m0 = half8_to_f4(mb, b);
        float d0 = qv.x * k0.x + qv.y * k0.y + qv.z * k0.z + qv.w * k0.w;
        d0 += __shfl_xor_sync(0xffffffffu, d0, 1);
        d0 += __shfl_xor_sync(0xffffffffu, d0, 2);
        float a0 = __expf(d0 * ph);
        den += a0;
        acc.x += a0 * m0.x; acc.y += a0 * m0.y;
        acc.z += a0 * m0.z; acc.w += a0 * m0.w;
    }

    float inv = (den > 0.f) ? (1.f / den) : 0.f;
    float gl[4];
    gl[0] = gelu_exact(acc.x * inv);
    gl[1] = gelu_exact(acc.y * inv);
    gl[2] = gelu_exact(acc.z * inv);
    gl[3] = gelu_exact(acc.w * inv);

    float o[8] = {0, 0, 0, 0, 0, 0, 0, 0};
    int r0 = lane * 4;
#pragma unroll
    for (int j = 0; j < 4; j++) {
        float gj = gl[j];
        const float* wr = &sWc[(r0 + j) * 8];
#pragma unroll
        for (int c = 0; c < 8; c++) o[c] += gj * wr[c];
    }
#pragma unroll
    for (int off = 16; off > 0; off >>= 1)
#pragma unroll
        for (int c = 0; c < 8; c++) o[c] += __shfl_xor_sync(0xffffffffu, o[c], off);

    if (lane == 0) {
        float g = sc[0];
        const float* s0p = &d_s0[(size_t)node * 8];
        float4 o1, o2;
        o1.x = g * o[0] + (1.f - g) * s0p[0] + sc[1];
        o1.y = g * o[1] + (1.f - g) * s0p[1] + sc[2];
        o1.z = g * o[2] + (1.f - g) * s0p[2] + sc[3];
        o1.w = g * o[3] + (1.f - g) * s0p[3] + sc[4];
        o2.x = g * o[4] + (1.f - g) * s0p[4] + sc[5];
        o2.y = g * o[5] + (1.f - g) * s0p[5] + sc[6];
        o2.z = g * o[6] + (1.f - g) * s0p[6] + sc[7];
        o2.w = g * o[7] + (1.f - g) * s0p[7] + sc[8];
        *(float4*)&out[(size_t)node * 8] = o1;
        *(float4*)&out[(size_t)node * 8 + 4] = o2;
    }
}

// ---------------- launch ----------------
#define SYM(p, s) cudaGetSymbolAddress((void**)&(p), s)

extern "C" void kernel_launch(void* const* d_in, const int* in_sizes, int n_in,
                              void* d_out, int out_size) {
    (void)in_sizes; (void)n_in; (void)out_size;
    const float* x_m   = (const float*)d_in[0];
    const float* x_d   = (const float*)d_in[1];
    const float* x_a   = (const float*)d_in[2];
    const int* src_dm  = (const int*)d_in[3];
    const int* dst_dm  = (const int*)d_in[4];
    const int* src_am  = (const int*)d_in[5];
    const int* dst_am  = (const int*)d_in[6];
    const float* Wpre_m = (const float*)d_in[11];
    const float* Wpre_d = (const float*)d_in[12];
    const float* Wpre_a = (const float*)d_in[13];
    const float* bpre   = (const float*)d_in[14];
    const float* Wk     = (const float*)d_in[15];
    const float* bk     = (const float*)d_in[16];
    const float* Wq     = (const float*)d_in[17];
    const float* bq     = (const float*)d_in[18];
    const float* Wv     = (const float*)d_in[19];
    const float* bv     = (const float*)d_in[20];
    const float* a_rel  = (const float*)d_in[21];
    const float* m_rel  = (const float*)d_in[22];
    const float* p_rel  = (const float*)d_in[23];
    const float* skip   = (const float*)d_in[24];
    const float* Wa     = (const float*)d_in[25];
    const float* ba     = (const float*)d_in[26];
    const float* Wlin   = (const float*)d_in[27];
    const float* blin   = (const float*)d_in[28];
    float* out = (float*)d_out;

    int* counts;
    SYM(counts, d_counts);

    const int SMEM_G = 36864 + 20480 + 8192;   // 65536 B

    // lazy one-time setup (runs on the first, non-captured, correctness call)
    static cudaStream_t s2 = nullptr;
    static cudaEvent_t evFork = nullptr, evJoin = nullptr;
    if (!s2) {
        cudaFuncSetAttribute(gemm_all, cudaFuncAttributeMaxDynamicSharedMemorySize, SMEM_G);
        cudaStreamCreateWithFlags(&s2, cudaStreamNonBlocking);
        cudaEventCreateWithFlags(&evFork, cudaEventDisableTiming);
        cudaEventCreateWithFlags(&evJoin, cudaEventDisableTiming);
    }

    // ---- fork: CSR build on side stream, overlapped with weight prep + GEMMs ----
    cudaEventRecord(evFork, 0);
    cudaStreamWaitEvent(s2, evFork, 0);

    // branch B (s2): CSR by destination movie node
    cudaMemsetAsync(counts, 0, NM * sizeof(int), s2);
    count_edges<<<2344, 256, 0, s2>>>(dst_dm, dst_am);
    scan_block<<<NB, 1024, 0, s2>>>();
    scan_bsum<<<1, 32, 0, s2>>>();
    add_offsets<<<391, 256, 0, s2>>>();
    fill_edges<<<2344, 256, 0, s2>>>(dst_dm, dst_am, src_dm, src_am);
    cudaEventRecord(evJoin, s2);

    // branch A (stream 0): weight prep + all node-level GEMMs (fp16 MMA)
    prep_compose<<<516, 128>>>(Wk, bk, Wv, bv, a_rel, m_rel);
    prep_mm<<<403, 256>>>(Wpre_m, Wpre_d, Wpre_a, bpre, Wq, bq, Wa, ba, Wlin);
    gemm_all<<<1878, 256, SMEM_G>>>(x_m, x_d, x_a);

    // ---- join: attention aggregation needs both branches ----
    cudaStreamWaitEvent(0, evJoin, 0);
    agg_out<<<12500, 256>>>(p_rel, skip, blin, out);
}

// round 16
// speedup vs baseline: 1.1337x; 1.0030x over previous
#include <cuda_runtime.h>
#include <cuda_fp16.h>
#include <math.h>
#include <stdint.h>

#define NM 100000
#define ND 20000
#define NA 50000
#define E0 300000
#define ETOT 600000
#define NB 98   // ceil(NM/1024)

// ---------------- scratch (static device memory; no allocs) ----------------
__device__ __half d_q0h[NM * 128];
__device__ float  d_s0[NM * 8];
__device__ __half d_ktdm[ND * 128];
__device__ __half d_mtdm[ND * 128];
__device__ __half d_ktam[NA * 128];
__device__ __half d_mtam[NA * 128];
__device__ int    d_counts[NM];
__device__ int    d_cursor[NM];
__device__ int    d_rowptr[NM + 1];
__device__ int    d_bsum[128];
__device__ int    d_epay[ETOT];   // packed: src | (rel<<31)

__device__ float d_WeffK0[128 * 128], d_WeffV0[128 * 128];
__device__ float d_WeffK1[128 * 128], d_WeffV1[128 * 128];
__device__ float d_beffK0[128], d_beffV0[128], d_beffK1[128], d_beffV1[128];
// fp16 transposed weights for the MMA GEMMs: Wt[n][k]
__device__ __half d_WqfT[128 * 256];
__device__ __half d_WK0T[128 * 128], d_WV0T[128 * 128];
__device__ __half d_WK1T[128 * 128], d_WV1T[128 * 128];
__device__ float d_bK0[128], d_bV0[128], d_bK1[128], d_bV1[128];
__device__ float d_bqf[128];
__device__ float d_Wsf[256 * 8];
__device__ float d_bsf[8];
__device__ float d_Wcomb[128 * 8];
__device__ float d_tmp8[8];

// ---------------- fused weight-composition kernels ----------------

__global__ void prep_compose(const float* __restrict__ Wk, const float* __restrict__ bk,
                             const float* __restrict__ Wv, const float* __restrict__ bv,
                             const float* __restrict__ a_rel, const float* __restrict__ m_rel) {
    int which = blockIdx.x / 129;
    int i = blockIdx.x - which * 129;
    const float *Win, *bin, *A; float *Weff, *beff;
    switch (which) {
        case 0: Win = Wk + 16384; bin = bk + 128; A = a_rel;        Weff = d_WeffK0; beff = d_beffK0; break;
        case 1: Win = Wk + 32768; bin = bk + 256; A = a_rel + 2048; Weff = d_WeffK1; beff = d_beffK1; break;
        case 2: Win = Wv + 16384; bin = bv + 128; A = m_rel;        Weff = d_WeffV0; beff = d_beffV0; break;
        default:Win = Wv + 32768; bin = bv + 256; A = m_rel + 2048; Weff = d_WeffV1; beff = d_beffV1; break;
    }
    int col = threadIdx.x;
    int h = col >> 4, f = col & 15;
    const float* arow = A + h * 256 + f;
    const float* w = (i < 128) ? (Win + i * 128 + h * 16) : (bin + h * 16);
    float s = 0.f;
#pragma unroll
    for (int d = 0; d < 16; d++) s += w[d] * arow[d * 16];
    if (i < 128) Weff[i * 128 + col] = s;
    else         beff[col] = s;
}

// f32 output variant (biases + thin-GEMM weights)
__device__ __forceinline__ void mm_task(const float* __restrict__ A, const float* __restrict__ B,
                                        const float* __restrict__ add, float* __restrict__ C,
                                        int M, int K, int N, int t) {
    if (t >= M * N) return;
    int m = t / N, n = t - m * N;
    float s = add ? add[n] : 0.f;
    for (int k = 0; k < K; k++) s += A[m * K + k] * B[k * N + n];
    C[t] = s;
}

// fp16 TRANSPOSED output variant: Ct[n][m] = sum_k A[m][k] B[k][n]
__device__ __forceinline__ void mm_task_h(const float* __restrict__ A, const float* __restrict__ B,
                                          __half* __restrict__ Ct,
                                          int M, int K, int N, int t) {
    if (t >= M * N) return;
    int m = t / N, n = t - m * N;
    float s = 0.f;
    for (int k = 0; k < K; k++) s += A[m * K + k] * B[k * N + n];
    Ct[n * M + m] = __float2half_rn(s);
}

__global__ void prep_mm(const float* __restrict__ Wpre_m, const float* __restrict__ Wpre_d,
                        const float* __restrict__ Wpre_a, const float* __restrict__ bpre,
                        const float* __restrict__ Wq, const float* __restrict__ bq,
                        const float* __restrict__ Wa, const float* __restrict__ ba,
                        const float* __restrict__ Wlin) {
    int b = blockIdx.x;
    int tid = threadIdx.x;
    if (b < 64)        mm_task_h(Wpre_d, d_WeffK0, d_WK0T, 128, 128, 128, b * 256 + tid);
    else if (b < 128)  mm_task_h(Wpre_d, d_WeffV0, d_WV0T, 128, 128, 128, (b - 64) * 256 + tid);
    else if (b < 192)  mm_task_h(Wpre_a, d_WeffK1, d_WK1T, 128, 128, 128, (b - 128) * 256 + tid);
    else if (b < 256)  mm_task_h(Wpre_a, d_WeffV1, d_WV1T, 128, 128, 128, (b - 192) * 256 + tid);
    else if (b < 384)  mm_task_h(Wpre_m, Wq, d_WqfT, 256, 128, 128, (b - 256) * 256 + tid);
    else if (b == 384) mm_task(bpre + 128, d_WeffK0, d_beffK0, d_bK0, 1, 128, 128, tid);
    else if (b == 385) mm_task(bpre + 128, d_WeffV0, d_beffV0, d_bV0, 1, 128, 128, tid);
    else if (b == 386) mm_task(bpre + 256, d_WeffK1, d_beffK1, d_bK1, 1, 128, 128, tid);
    else if (b == 387) mm_task(bpre + 256, d_WeffV1, d_beffV1, d_bV1, 1, 128, 128, tid);
    else if (b == 388) mm_task(bpre, Wq, bq, d_bqf, 1, 128, 128, tid);
    else if (b < 397)  mm_task(Wpre_m, Wlin, nullptr, d_Wsf, 256, 128, 8, (b - 389) * 256 + tid);
    else if (b == 397) mm_task(bpre, Wlin, nullptr, d_bsf, 1, 128, 8, tid);
    else if (b < 402)  mm_task(Wa, Wlin, nullptr, d_Wcomb, 128, 128, 8, (b - 398) * 256 + tid);
    else               mm_task(ba, Wlin, nullptr, d_tmp8, 1, 128, 8, tid);
}

// ---------------- pipelined fp16 tensor-core GEMM ----------------
__device__ __forceinline__ void cpa16(void* s, const void* g, int psz) {
    uint32_t sa = (uint32_t)__cvta_generic_to_shared(s);
    asm volatile("cp.async.cg.shared.global [%0], [%1], 16, %2;" :: "r"(sa), "l"(g), "r"(psz));
}

template<int KT, bool FS0, bool HOUT>
__device__ __forceinline__ void gemm_body(const float* __restrict__ A, const __half* __restrict__ Wt,
                                          const float* __restrict__ bias, void* __restrict__ Cv,
                                          int M, int row0,
                                          const float* __restrict__ Wsf, const float* __restrict__ bsf,
                                          float* __restrict__ S) {
    extern __shared__ char smem_raw[];
    float*  AsBase = (float*)smem_raw;                    // 2 * 128 * 36 floats
    __half* BsBase = (__half*)(smem_raw + 36864);         // 2 * 128 * 40 halves
    float*  sWs    = (float*)(smem_raw + 36864 + 20480);  // 2048 floats

    const int K = KT * 32;
    int tid = threadIdx.x;
    int warp = tid >> 5, lane = tid & 31;
    int wm = warp >> 1, wn = warp & 1;
    int g = lane >> 2, tg = lane & 3;

    if (FS0) {
        for (int i = tid; i < 2048; i += 256) sWs[i] = Wsf[i];
    }

    float acc[2][8][4];
#pragma unroll
    for (int mi = 0; mi < 2; mi++)
#pragma unroll
        for (int ni = 0; ni < 8; ni++)
#pragma unroll
            for (int c = 0; c < 4; c++) acc[mi][ni][c] = 0.f;
    float sacc[4] = {0.f, 0.f, 0.f, 0.f};

    auto load_tile = [&](int kt, int buf) {
        float*  Ab = AsBase + buf * (128 * 36);
        __half* Bb = BsBase + buf * (128 * 40);
#pragma unroll
        for (int l = 0; l < 4; l++) {
            int cidx = tid + l * 256;
            int r = cidx >> 3, q = cidx & 7;
            int gr = row0 + r;
            const float* ga = (gr < M) ? &A[(size_t)gr * K + kt * 32 + q * 4] : A;
            cpa16(&Ab[r * 36 + q * 4], ga, (gr < M) ? 16 : 0);
        }
#pragma unroll
        for (int l = 0; l < 2; l++) {
            int cidx = tid + l * 256;            // 0..511
            int col = cidx >> 2, q = (cidx & 3) * 8;
            cpa16(&Bb[col * 40 + q], &Wt[(size_t)col * K + kt * 32 + q], 16);
        }
        asm volatile("cp.async.commit_group;");
    };

    load_tile(0, 0);

    for (int t = 0; t < KT; t++) {
        if (t + 1 < KT) {
            load_tile(t + 1, (t + 1) & 1);
            asm volatile("cp.async.wait_group 1;");
        } else {
            asm volatile("cp.async.wait_group 0;");
        }
        __syncthreads();

        float*  Ab = AsBase + (t & 1) * (128 * 36);
        __half* Bb = BsBase + (t & 1) * (128 * 40);

#pragma unroll
        for (int ks = 0; ks < 32; ks += 16) {
            int c = ks + tg * 2;
            uint32_t a_[2][4];
#pragma unroll
            for (int mi = 0; mi < 2; mi++) {
                int ar = wm * 32 + mi * 16 + g;
                float2 v0 = *(const float2*)&Ab[ar * 36 + c];
                float2 v1 = *(const float2*)&Ab[(ar + 8) * 36 + c];
                float2 v2 = *(const float2*)&Ab[ar * 36 + c + 8];
                float2 v3 = *(const float2*)&Ab[(ar + 8) * 36 + c + 8];
                __half2 h0 = __floats2half2_rn(v0.x, v0.y);
                __half2 h1 = __floats2half2_rn(v1.x, v1.y);
                __half2 h2 = __floats2half2_rn(v2.x, v2.y);
                __half2 h3 = __floats2half2_rn(v3.x, v3.y);
                a_[mi][0] = *(uint32_t*)&h0;
                a_[mi][1] = *(uint32_t*)&h1;
                a_[mi][2] = *(uint32_t*)&h2;
                a_[mi][3] = *(uint32_t*)&h3;
            }
#pragma unroll
            for (int ni = 0; ni < 8; ni++) {
                int bc = wn * 64 + ni * 8 + g;
                uint32_t b0 = *(const uint32_t*)&Bb[bc * 40 + c];
                uint32_t b1 = *(const uint32_t*)&Bb[bc * 40 + c + 8];
#pragma unroll
                for (int mi = 0; mi < 2; mi++) {
                    asm volatile(
                        "mma.sync.aligned.m16n8k16.row.col.f32.f16.f16.f32 "
                        "{%0,%1,%2,%3}, {%4,%5,%6,%7}, {%8,%9}, {%0,%1,%2,%3};"
                        : "+f"(acc[mi][ni][0]), "+f"(acc[mi][ni][1]),
                          "+f"(acc[mi][ni][2]), "+f"(acc[mi][ni][3])
                        : "r"(a_[mi][0]), "r"(a_[mi][1]), "r"(a_[mi][2]), "r"(a_[mi][3]),
                          "r"(b0), "r"(b1));
                }
            }
        }

        if (FS0) {
            int r = tid >> 1, cg4 = (tid & 1) * 4;
            const float* Ar = &Ab[r * 36];
            const float* Wr = &sWs[t * 32 * 8 + cg4];
#pragma unroll
            for (int kk = 0; kk < 32; kk++) {
                float av = Ar[kk];
                float4 w = *(const float4*)&Wr[kk * 8];
                sacc[0] += av * w.x; sacc[1] += av * w.y;
                sacc[2] += av * w.z; sacc[3] += av * w.w;
            }
        }
        __syncthreads();
    }

#pragma unroll
    for (int mi = 0; mi < 2; mi++) {
#pragma unroll
        for (int ni = 0; ni < 8; ni++) {
            int col = wn * 64 + ni * 8 + tg * 2;
            float bx = bias[col], by = bias[col + 1];
            int r1 = row0 + wm * 32 + mi * 16 + g;
            int r2 = r1 + 8;
            if (HOUT) {
                __half* C = (__half*)Cv;
                if (r1 < M)
                    *(__half2*)&C[(size_t)r1 * 128 + col] =
                        __floats2half2_rn(acc[mi][ni][0] + bx, acc[mi][ni][1] + by);
                if (r2 < M)
                    *(__half2*)&C[(size_t)r2 * 128 + col] =
                        __floats2half2_rn(acc[mi][ni][2] + bx, acc[mi][ni][3] + by);
            } else {
                float* C = (float*)Cv;
                if (r1 < M) {
                    float2 o = make_float2(acc[mi][ni][0] + bx, acc[mi][ni][1] + by);
                    *(float2*)&C[(size_t)r1 * 128 + col] = o;
                }
                if (r2 < M) {
                    float2 o = make_float2(acc[mi][ni][2] + bx, acc[mi][ni][3] + by);
                    *(float2*)&C[(size_t)r2 * 128 + col] = o;
                }
            }
        }
    }

    if (FS0) {
        int r = tid >> 1, cg4 = (tid & 1) * 4;
        int gr = row0 + r;
        if (gr < M) {
            float4 o;
            o.x = sacc[0] + bsf[cg4 + 0];
            o.y = sacc[1] + bsf[cg4 + 1];
            o.z = sacc[2] + bsf[cg4 + 2];
            o.w = sacc[3] + bsf[cg4 + 3];
            *(float4*)&S[(size_t)gr * 8 + cg4] = o;
        }
    }
}

// single merged GEMM launch: q0 (fp16 out + fused s0, K=256) + 4 K/V GEMMs (K=128, fp16 out)
__global__ __launch_bounds__(256, 2)
void gemm_all(const float* __restrict__ x_m, const float* __restrict__ x_d,
              const float* __restrict__ x_a) {
    int b = blockIdx.x;
    if (b < 782) {
        gemm_body<8, true, true>(x_m, d_WqfT, d_bqf, d_q0h, NM, b * 128, d_Wsf, d_bsf, d_s0);
        return;
    }
    b -= 782;
    if (b < 157)      gemm_body<4, false, true>(x_d, d_WK0T, d_bK0, d_ktdm, ND, b * 128, nullptr, nullptr, nullptr);
    else if (b < 314) gemm_body<4, false, true>(x_d, d_WV0T, d_bV0, d_mtdm, ND, (b - 157) * 128, nullptr, nullptr, nullptr);
    else if (b < 705) gemm_body<4, false, true>(x_a, d_WK1T, d_bK1, d_ktam, NA, (b - 314) * 128, nullptr, nullptr, nullptr);
    else              gemm_body<4, false, true>(x_a, d_WV1T, d_bV1, d_mtam, NA, (b - 705) * 128, nullptr, nullptr, nullptr);
}

// ---------------- CSR build (counting sort by destination movie node) ----------------
__global__ void count_edges(const int* __restrict__ dst_dm, const int* __restrict__ dst_am) {
    int e = blockIdx.x * blockDim.x + threadIdx.x;
    if (e < E0) atomicAdd(&d_counts[dst_dm[e]], 1);
    else if (e < ETOT) atomicAdd(&d_counts[dst_am[e - E0]], 1);
}
__global__ void scan_block() {
    __shared__ int sh[1024];
    int i = blockIdx.x * 1024 + threadIdx.x;
    int v = (i < NM) ? d_counts[i] : 0;
    sh[threadIdx.x] = v;
    __syncthreads();
    for (int off = 1; off < 1024; off <<= 1) {
        int t = (threadIdx.x >= off) ? sh[threadIdx.x - off] : 0;
        __syncthreads();
        sh[threadIdx.x] += t;
        __syncthreads();
    }
    if (i < NM) d_rowptr[i] = sh[threadIdx.x] - v;
    if (threadIdx.x == 1023) d_bsum[blockIdx.x] = sh[1023];
}
__global__ void scan_bsum() {
    if (threadIdx.x == 0) {
        int s = 0;
        for (int b = 0; b < NB; b++) { int v = d_bsum[b]; d_bsum[b] = s; s += v; }
    }
}
__global__ void add_offsets() {
    int i = blockIdx.x * blockDim.x + threadIdx.x;
    if (i < NM) {
        int v = d_rowptr[i] + d_bsum[i >> 10];
        d_rowptr[i] = v;
        d_cursor[i] = v;
    }
    if (i == 0) d_rowptr[NM] = ETOT;
}
__global__ void fill_edges(const int* __restrict__ dst_dm, const int* __restrict__ dst_am,
                           const int* __restrict__ src_dm, const int* __restrict__ src_am) {
    int e = blockIdx.x * blockDim.x + threadIdx.x;
    int d, pay;
    if (e < E0)       { d = dst_dm[e];      pay = src_dm[e]; }
    else if (e < ETOT){ d = dst_am[e - E0]; pay = src_am[e - E0] | 0x80000000; }
    else return;
    int pos = atomicAdd(&d_cursor[d], 1);
    d_epay[pos] = pay;
}

// ---------------- fused: per-edge attention + softmax-agg + gelu + output head ----------------
__device__ __forceinline__ float gelu_exact(float x) { return x * normcdff(x); }

__device__ __forceinline__ float4 half8_to_f4(const __half* base, size_t off) {
    uint2 w = *(const uint2*)(base + off);
    float2 lo = __half22float2(*(__half2*)&w.x);
    float2 hi = __half22float2(*(__half2*)&w.y);
    return make_float4(lo.x, lo.y, hi.x, hi.y);
}

__global__ __launch_bounds__(256)
void agg_out(const float* __restrict__ p_rel, const float* __restrict__ skip,
             const float* __restrict__ blin, float* __restrict__ out) {
    __shared__ float sWc[128 * 8];
    __shared__ float sc[9];
    for (int i = threadIdx.x; i < 1024; i += 256) sWc[i] = d_Wcomb[i];
    if (threadIdx.x < 8) {
        float gg = 1.f / (1.f + expf(-skip[0]));
        sc[1 + threadIdx.x] = gg * d_tmp8[threadIdx.x] + blin[threadIdx.x];
        if (threadIdx.x == 0) sc[0] = gg;
    }
    __syncthreads();

    int warp = threadIdx.x >> 5, lane = threadIdx.x & 31;
    int node = blockIdx.x * 8 + warp;
    int h = lane >> 2;
    const float scale = 0.25f;
    float p0 = p_rel[h] * scale;
    float p1 = p_rel[8 + h] * scale;

    float4 qv = half8_to_f4(d_q0h, (size_t)node * 128 + lane * 4);
    int beg = d_rowptr[node], end = d_rowptr[node + 1];

    float4 acc = make_float4(0.f, 0.f, 0.f, 0.f);
    float den = 0.f;

    // Cooperative payload prefetch: one coalesced load per 32-edge chunk, then
    // shfl-broadcast. Gather addresses no longer wait on a serial payload load.
    for (int base = beg; base < end; base += 32) {
        int n = end - base;
        if (n > 32) n = 32;
        int mypay = (lane < n) ? d_epay[base + lane] : 0;
        int j = 0;
        for (; j + 2 <= n; j += 2) {
            int pay0 = __shfl_sync(0xffffffffu, mypay, j);
            int pay1 = __shfl_sync(0xffffffffu, mypay, j + 1);
            unsigned u0 = (unsigned)pay0, u1 = (unsigned)pay1;
            int src0 = pay0 & 0x7FFFFFFF, src1 = pay1 & 0x7FFFFFFF;
            const __half* kb0 = (u0 >> 31) ? d_ktam : d_ktdm;
            const __half* mb0 = (u0 >> 31) ? d_mtam : d_mtdm;
            const __half* kb1 = (u1 >> 31) ? d_ktam : d_ktdm;
            const __half* mb1 = (u1 >> 31) ? d_mtam : d_mtdm;
            float ph0 = (u0 >> 31) ? p1 : p0;
            float ph1 = (u1 >> 31) ? p1 : p0;
            size_t b0 = (size_t)src0 * 128 + lane * 4;
            size_t b1 = (size_t)src1 * 128 + lane * 4;
            float4 k0 = half8_to_f4(kb0, b0);
            float4 m0 = half8_to_f4(mb0, b0);
            float4 k1 = half8_to_f4(kb1, b1);
            float4 m1 = half8_to_f4(mb1, b1);
            float d0 = qv.x * k0.x + qv.y * k0.y + qv.z * k0.z + qv.w * k0.w;
            float d1 = qv.x * k1.x + qv.y * k1.y + qv.z * k1.z + qv.w * k1.w;
            d0 += __shfl_xor_sync(0xffffffffu, d0, 1);
            d1 += __shfl_xor_sync(0xffffffffu, d1, 1);
            d0 += __shfl_xor_sync(0xffffffffu, d0, 2);
            d1 += __shfl_xor_sync(0xffffffffu, d1, 2);
            float a0 = __expf(d0 * ph0);
            float a1 = __expf(d1 * ph1);
            den += a0 + a1;
            acc.x += a0 * m0.x + a1 * m1.x;
            acc.y += a0 * m0.y + a1 * m1.y;
            acc.z += a0 * m0.z + a1 * m1.z;
            acc.w += a0 * m0.w + a1 * m1.w;
        }
        if (j < n) {
            int pay = __shfl_sync(0xffffffffu, mypay, j);
            unsigned u = (unsigned)pay;
            int src = pay & 0x7FFFFFFF;
            const __half* kb = (u >> 31) ? d_ktam : d_ktdm;
            const __half* mb = (u >> 31) ? d_mtam : d_mtdm;
            float ph = (u >> 31) ? p1 : p0;
            size_t b = (size_t)src * 128 + lane * 4;
            float4 k0 = half8_to_f4(kb, b);
            float4 m0 = half8_to_f4(mb, b);
            float d0 = qv.x * k0.x + qv.y * k0.y + qv.z * k0.z + qv.w * k0.w;
            d0 += __shfl_xor_sync(0xffffffffu, d0, 1);
            d0 += __shfl_xor_sync(0xffffffffu, d0, 2);
            float a0 = __expf(d0 * ph);
            den += a0;
            acc.x += a0 * m0.x; acc.y += a0 * m0.y;
            acc.z += a0 * m0.z; acc.w += a0 * m0.w;
        }
    }

    float inv = (den > 0.f) ? (1.f / den) : 0.f;
    float gl[4];
    gl[0] = gelu_exact(acc.x * inv);
    gl[1] = gelu_exact(acc.y * inv);
    gl[2] = gelu_exact(acc.z * inv);
    gl[3] = gelu_exact(acc.w * inv);

    float o[8] = {0, 0, 0, 0, 0, 0, 0, 0};
    int r0 = lane * 4;
#pragma unroll
    for (int j = 0; j < 4; j++) {
        float gj = gl[j];
        const float* wr = &sWc[(r0 + j) * 8];
#pragma unroll
        for (int c = 0; c < 8; c++) o[c] += gj * wr[c];
    }
#pragma unroll
    for (int off = 16; off > 0; off >>= 1)
#pragma unroll
        for (int c = 0; c < 8; c++) o[c] += __shfl_xor_sync(0xffffffffu, o[c], off);

    if (lane == 0) {
        float g = sc[0];
        const float* s0p = &d_s0[(size_t)node * 8];
        float4 o1, o2;
        o1.x = g * o[0] + (1.f - g) * s0p[0] + sc[1];
        o1.y = g * o[1] + (1.f - g) * s0p[1] + sc[2];
        o1.z = g * o[2] + (1.f - g) * s0p[2] + sc[3];
        o1.w = g * o[3] + (1.f - g) * s0p[3] + sc[4];
        o2.x = g * o[4] + (1.f - g) * s0p[4] + sc[5];
        o2.y = g * o[5] + (1.f - g) * s0p[5] + sc[6];
        o2.z = g * o[6] + (1.f - g) * s0p[6] + sc[7];
        o2.w = g * o[7] + (1.f - g) * s0p[7] + sc[8];
        *(float4*)&out[(size_t)node * 8] = o1;
        *(float4*)&out[(size_t)node * 8 + 4] = o2;
    }
}

// ---------------- launch ----------------
#define SYM(p, s) cudaGetSymbolAddress((void**)&(p), s)

extern "C" void kernel_launch(void* const* d_in, const int* in_sizes, int n_in,
                              void* d_out, int out_size) {
    (void)in_sizes; (void)n_in; (void)out_size;
    const float* x_m   = (const float*)d_in[0];
    const float* x_d   = (const float*)d_in[1];
    const float* x_a   = (const float*)d_in[2];
    const int* src_dm  = (const int*)d_in[3];
    const int* dst_dm  = (const int*)d_in[4];
    const int* src_am  = (const int*)d_in[5];
    const int* dst_am  = (const int*)d_in[6];
    const float* Wpre_m = (const float*)d_in[11];
    const float* Wpre_d = (const float*)d_in[12];
    const float* Wpre_a = (const float*)d_in[13];
    const float* bpre   = (const float*)d_in[14];
    const float* Wk     = (const float*)d_in[15];
    const float* bk     = (const float*)d_in[16];
    const float* Wq     = (const float*)d_in[17];
    const float* bq     = (const float*)d_in[18];
    const float* Wv     = (const float*)d_in[19];
    const float* bv     = (const float*)d_in[20];
    const float* a_rel  = (const float*)d_in[21];
    const float* m_rel  = (const float*)d_in[22];
    const float* p_rel  = (const float*)d_in[23];
    const float* skip   = (const float*)d_in[24];
    const float* Wa     = (const float*)d_in[25];
    const float* ba     = (const float*)d_in[26];
    const float* Wlin   = (const float*)d_in[27];
    const float* blin   = (const float*)d_in[28];
    float* out = (float*)d_out;

    int* counts;
    SYM(counts, d_counts);

    const int SMEM_G = 36864 + 20480 + 8192;   // 65536 B

    // lazy one-time setup (runs on the first, non-captured, correctness call)
    static cudaStream_t s2 = nullptr;
    static cudaEvent_t evFork = nullptr, evJoin = nullptr;
    if (!s2) {
        cudaFuncSetAttribute(gemm_all, cudaFuncAttributeMaxDynamicSharedMemorySize, SMEM_G);
        cudaStreamCreateWithFlags(&s2, cudaStreamNonBlocking);
        cudaEventCreateWithFlags(&evFork, cudaEventDisableTiming);
        cudaEventCreateWithFlags(&evJoin, cudaEventDisableTiming);
    }

    // ---- fork: CSR build on side stream, overlapped with weight prep + GEMMs ----
    cudaEventRecord(evFork, 0);
    cudaStreamWaitEvent(s2, evFork, 0);

    // Submission order chosen so gemm_all is the 5th device op (ncu window lands there).
    cudaMemsetAsync(counts, 0, NM * sizeof(int), s2);                        // 1
    count_edges<<<2344, 256, 0, s2>>>(dst_dm, dst_am);                       // 2
    prep_compose<<<516, 128>>>(Wk, bk, Wv, bv, a_rel, m_rel);                // 3 (s0)
    prep_mm<<<403, 256>>>(Wpre_m, Wpre_d, Wpre_a, bpre, Wq, bq, Wa, ba, Wlin); // 4 (s0)
    gemm_all<<<1878, 256, SMEM_G>>>(x_m, x_d, x_a);                          // 5 (s0) ← profile target
    scan_block<<<NB, 1024, 0, s2>>>();                                       // 6
    scan_bsum<<<1, 32, 0, s2>>>();                                           // 7
    add_offsets<<<391, 256, 0, s2>>>();                                      // 8
    fill_edges<<<2344, 256, 0, s2>>>(dst_dm, dst_am, src_dm, src_am);        // 9
    cudaEventRecord(evJoin, s2);

    // ---- join: attention aggregation needs both branches ----
    cudaStreamWaitEvent(0, evJoin, 0);
    agg_out<<<12500, 256>>>(p_rel, skip, blin, out);
}